// round 1
// baseline (speedup 1.0000x reference)
#include <cuda_runtime.h>
#include <cuda_bf16.h>
#include <math.h>

// ---------------- problem constants ----------------
#define C_IN     256
#define H_M      272
#define W_M      480
#define HW_M     (H_M * W_M)          // 130560
#define H_H      136
#define W_H      240
#define HW_H     (H_H * W_H)          // 32640
#define MB_CH    64
#define NUM_INS  4
#define NGP      134                  // gen params per instance
#define NMP      67                   // mask params (66 w + 1 b)
#define HID      64

// output layout (float32, concatenated flatten of reference tuple)
#define OFF_SCORES 0
#define OFF_INDS   4
#define OFF_REGS   8
#define OFF_MASKS  (8 + NUM_INS * HW_M)              // 522248
#define OFF_FEAT   (OFF_MASKS + NUM_INS * HW_M)      // 1044488

// ---------------- device scratch ----------------
__device__ float g_hm[HW_H];
__device__ float g_scores[NUM_INS];
__device__ int   g_inds[NUM_INS];
__device__ float g_gp[NUM_INS * NGP];
__device__ float g_tw[C_IN * 9 * MB_CH];   // weights transposed to [c][tap][oc]

// ---------------- kernel 0: transpose conv weights to [c][tap][oc] ----------------
__global__ void k_transw(const float* __restrict__ mb_w) {
    int idx = blockIdx.x * 256 + threadIdx.x;
    if (idx < C_IN * 9 * MB_CH) {
        int oc = idx & 63;
        int rest = idx >> 6;
        int t = rest % 9;
        int c = rest / 9;
        g_tw[idx] = mb_w[oc * (C_IN * 9) + c * 9 + t];
    }
}

// ---------------- kernel 1: heatmap head (sigmoid + clip) ----------------
__global__ void k_hm(const float* __restrict__ out1,
                     const float* __restrict__ hm_w,
                     const float* __restrict__ hm_b) {
    int p = blockIdx.x * 256 + threadIdx.x;
    if (p >= HW_H) return;
    float s = hm_b[0];
    #pragma unroll 8
    for (int c = 0; c < C_IN; c++)
        s += hm_w[c] * out1[c * HW_H + p];
    float sg = 1.0f / (1.0f + expf(-s));
    sg = fminf(fmaxf(sg, 1e-4f), 1.0f - 1e-4f);
    g_hm[p] = sg;
}

// ---------------- kernel 2: 3x3 NMS + top-4 (single block, 1024 threads) ----------------
__device__ __forceinline__ bool tk_better(float v1, int i1, float v2, int i2) {
    return (v1 > v2) || (v1 == v2 && i1 < i2);
}

__global__ void k_topk(float* __restrict__ dout) {
    __shared__ float sv[1024 * 4];
    __shared__ int   si[1024 * 4];
    int tid = threadIdx.x;

    float bv[4] = {-1.f, -1.f, -1.f, -1.f};
    int   bi[4] = {0x7fffffff, 0x7fffffff, 0x7fffffff, 0x7fffffff};

    for (int p = tid; p < HW_H; p += 1024) {
        int y = p / W_H, x = p % W_H;
        float v = g_hm[p];
        float mx = v;
        #pragma unroll
        for (int dy = -1; dy <= 1; dy++) {
            int yy = y + dy;
            if (yy < 0 || yy >= H_H) continue;
            #pragma unroll
            for (int dx = -1; dx <= 1; dx++) {
                int xx = x + dx;
                if (xx < 0 || xx >= W_H) continue;
                mx = fmaxf(mx, g_hm[yy * W_H + xx]);
            }
        }
        float heat = (mx == v) ? v : 0.0f;
        if (tk_better(heat, p, bv[3], bi[3])) {
            bv[3] = heat; bi[3] = p;
            #pragma unroll
            for (int j = 3; j >= 1; j--) {
                if (tk_better(bv[j], bi[j], bv[j - 1], bi[j - 1])) {
                    float tv = bv[j]; bv[j] = bv[j - 1]; bv[j - 1] = tv;
                    int ti = bi[j]; bi[j] = bi[j - 1]; bi[j - 1] = ti;
                }
            }
        }
    }
    #pragma unroll
    for (int j = 0; j < 4; j++) { sv[tid * 4 + j] = bv[j]; si[tid * 4 + j] = bi[j]; }

    for (int stride = 512; stride >= 1; stride >>= 1) {
        __syncthreads();
        if (tid < stride) {
            float av[4], cv[4], mv[4];
            int ai[4], ci[4], mi[4];
            #pragma unroll
            for (int j = 0; j < 4; j++) {
                av[j] = sv[tid * 4 + j];            ai[j] = si[tid * 4 + j];
                cv[j] = sv[(tid + stride) * 4 + j]; ci[j] = si[(tid + stride) * 4 + j];
            }
            int pa = 0, pb = 0;
            #pragma unroll
            for (int j = 0; j < 4; j++) {
                if (tk_better(av[pa], ai[pa], cv[pb], ci[pb])) { mv[j] = av[pa]; mi[j] = ai[pa]; pa++; }
                else                                          { mv[j] = cv[pb]; mi[j] = ci[pb]; pb++; }
            }
            #pragma unroll
            for (int j = 0; j < 4; j++) { sv[tid * 4 + j] = mv[j]; si[tid * 4 + j] = mi[j]; }
        }
    }
    __syncthreads();
    if (tid < 4) {
        g_scores[tid] = sv[tid];
        g_inds[tid] = si[tid];
        dout[OFF_SCORES + tid] = sv[tid];
        dout[OFF_INDS + tid]   = (float)si[tid];
    }
}

// ---------------- kernel 3: gen params only at the 4 selected pixels ----------------
__global__ void k_genparams(const float* __restrict__ out1,
                            const float* __restrict__ params_w,
                            const float* __restrict__ params_b) {
    int tid = threadIdx.x;
    if (tid >= NUM_INS * NGP) return;
    int ins = tid / NGP;
    int k = tid % NGP;
    int p = g_inds[ins];
    float s = params_b[k];
    #pragma unroll 8
    for (int c = 0; c < C_IN; c++)
        s += params_w[k * C_IN + c] * out1[c * HW_H + p];
    g_gp[ins * NGP + k] = s;
}

// ---------------- kernel 4: fused 3x3 conv + relu + dynamic heads ----------------
__global__ __launch_bounds__(256, 2)
void k_conv_heads(const float* __restrict__ out0,
                  const float* __restrict__ mb_b,
                  float* __restrict__ dout) {
    __shared__ float s_in[18 * 18];
    __shared__ float s_w[9 * MB_CH];
    __shared__ float s_gp[NUM_INS * NGP];
    __shared__ float s_mb[MB_CH];

    int tid = threadIdx.x;
    int tx = tid & 15, ty = tid >> 4;
    int x0 = blockIdx.x * 16, y0 = blockIdx.y * 16;

    for (int i = tid; i < NUM_INS * NGP; i += 256) s_gp[i] = g_gp[i];
    if (tid < MB_CH) s_mb[tid] = mb_b[tid];

    float acc[MB_CH];
    #pragma unroll
    for (int i = 0; i < MB_CH; i++) acc[i] = 0.0f;

    for (int c = 0; c < C_IN; c++) {
        __syncthreads();
        // input tile with halo (18x18), zero-padded at borders
        for (int i = tid; i < 324; i += 256) {
            int r = i / 18, col = i % 18;
            int gy = y0 + r - 1, gx = x0 + col - 1;
            float v = 0.0f;
            if (gy >= 0 && gy < H_M && gx >= 0 && gx < W_M)
                v = out0[c * HW_M + gy * W_M + gx];
            s_in[i] = v;
        }
        // weights for this channel: [tap][oc], contiguous
        for (int i = tid; i < 9 * MB_CH; i += 256)
            s_w[i] = g_tw[c * (9 * MB_CH) + i];
        __syncthreads();

        float in9[9];
        #pragma unroll
        for (int dy = 0; dy < 3; dy++)
            #pragma unroll
            for (int dx = 0; dx < 3; dx++)
                in9[dy * 3 + dx] = s_in[(ty + dy) * 18 + tx + dx];

        #pragma unroll
        for (int t = 0; t < 9; t++) {
            const float4* wv = (const float4*)(s_w + t * MB_CH);
            float iv = in9[t];
            #pragma unroll
            for (int q = 0; q < MB_CH / 4; q++) {
                float4 w = wv[q];
                acc[q * 4 + 0] += iv * w.x;
                acc[q * 4 + 1] += iv * w.y;
                acc[q * 4 + 2] += iv * w.z;
                acc[q * 4 + 3] += iv * w.w;
            }
        }
    }

    // bias + relu
    #pragma unroll
    for (int i = 0; i < MB_CH; i++) acc[i] = fmaxf(acc[i] + s_mb[i], 0.0f);

    int gx = x0 + tx, gy = y0 + ty;   // grids divide exactly (480=30*16, 272=17*16)
    float xx = -1.0f + 2.0f * (float)gx / (float)(W_M - 1);
    float yy = -1.0f + 2.0f * (float)gy / (float)(H_M - 1);
    int pix = gy * W_M + gx;

    #pragma unroll
    for (int ins = 0; ins < NUM_INS; ins++) {
        const float* gp = s_gp + ins * NGP;
        float m = gp[66] + gp[64] * xx + gp[65] * yy;
        float r = gp[133] + gp[NMP + 64] * xx + gp[NMP + 65] * yy;
        #pragma unroll
        for (int cc = 0; cc < MB_CH; cc++) {
            m += gp[cc] * acc[cc];
            r += gp[NMP + cc] * acc[cc];
        }
        dout[OFF_MASKS + ins * HW_M + pix] = m;
        dout[OFF_REGS  + ins * HW_M + pix] = r;
    }
}

// ---------------- kernel 5: per-column MLP over masks0 ----------------
__global__ void k_mlp(const float* __restrict__ w1, const float* __restrict__ b1,
                      const float* __restrict__ w2, const float* __restrict__ b2,
                      float* __restrict__ dout) {
    __shared__ float sh[4][HID];
    int tid = threadIdx.x;
    int lcol = tid / HID;      // 0..3
    int j = tid % HID;
    int g = blockIdx.x * 4 + lcol;   // 0..1919
    int ins = g / W_M;
    int x = g % W_M;
    const float* mbase = dout + OFF_MASKS + ins * HW_M + x;
    float s = b1[j];
    #pragma unroll 4
    for (int y = 0; y < H_M; y++)
        s += mbase[y * W_M] * w1[y * HID + j];
    sh[lcol][j] = fmaxf(s, 0.0f);
    __syncthreads();
    if (tid < 8) {
        int lc = tid >> 1, j2 = tid & 1;
        int gg = blockIdx.x * 4 + lc;
        float s2 = b2[j2];
        #pragma unroll
        for (int jj = 0; jj < HID; jj++)
            s2 += sh[lc][jj] * w2[jj * 2 + j2];
        dout[OFF_FEAT + gg * 2 + j2] = s2;
    }
}

// ---------------- launcher ----------------
extern "C" void kernel_launch(void* const* d_in, const int* in_sizes, int n_in,
                              void* d_out, int out_size) {
    const float* out0     = (const float*)d_in[0];
    const float* out1     = (const float*)d_in[1];
    const float* hm_w     = (const float*)d_in[2];
    const float* hm_b     = (const float*)d_in[3];
    const float* params_w = (const float*)d_in[4];
    const float* params_b = (const float*)d_in[5];
    const float* mb_w     = (const float*)d_in[6];
    const float* mb_b     = (const float*)d_in[7];
    const float* mlp_w1   = (const float*)d_in[8];
    const float* mlp_b1   = (const float*)d_in[9];
    const float* mlp_w2   = (const float*)d_in[10];
    const float* mlp_b2   = (const float*)d_in[11];
    float* dout = (float*)d_out;

    k_transw<<<(C_IN * 9 * MB_CH + 255) / 256, 256>>>(mb_w);
    k_hm<<<(HW_H + 255) / 256, 256>>>(out1, hm_w, hm_b);
    k_topk<<<1, 1024>>>(dout);
    k_genparams<<<1, 544>>>(out1, params_w, params_b);
    dim3 cgrid(W_M / 16, H_M / 16);
    k_conv_heads<<<cgrid, 256>>>(out0, mb_b, dout);
    k_mlp<<<(NUM_INS * W_M) / 4, 256>>>(mlp_w1, mlp_b1, mlp_w2, mlp_b2, dout);
}

// round 2
// speedup vs baseline: 1.1975x; 1.1975x over previous
#include <cuda_runtime.h>
#include <cuda_bf16.h>
#include <math.h>

// ---------------- problem constants ----------------
#define C_IN     256
#define H_M      272
#define W_M      480
#define HW_M     (H_M * W_M)          // 130560
#define H_H      136
#define W_H      240
#define HW_H     (H_H * W_H)          // 32640
#define MB_CH    64
#define NUM_INS  4
#define NGP      134                  // gen params per instance
#define NMP      67                   // mask params (66 w + 1 b)
#define HID      64

// output layout (float32, concatenated flatten of reference tuple)
#define OFF_SCORES 0
#define OFF_INDS   4
#define OFF_REGS   8
#define OFF_MASKS  (8 + NUM_INS * HW_M)              // 522248
#define OFF_FEAT   (OFF_MASKS + NUM_INS * HW_M)      // 1044488

// ---------------- device scratch ----------------
__device__ float g_hm[HW_H];
__device__ float g_scores[NUM_INS];
__device__ int   g_inds[NUM_INS];
__device__ float g_gp[NUM_INS * NGP];
__device__ float g_tw[C_IN * 9 * MB_CH];   // weights transposed to [c][tap][oc]
__device__ float g_pv[128 * 4];            // partial top-4 values
__device__ int   g_pi[128 * 4];            // partial top-4 indices

// ---------------- packed f32x2 helpers ----------------
__device__ __forceinline__ unsigned long long pack2(float v) {
    unsigned long long r;
    unsigned u = __float_as_uint(v);
    asm("mov.b64 %0, {%1, %1};" : "=l"(r) : "r"(u));
    return r;
}
__device__ __forceinline__ void fma2(unsigned long long& d,
                                     unsigned long long a,
                                     unsigned long long b) {
    asm("fma.rn.f32x2 %0, %1, %2, %0;" : "+l"(d) : "l"(a), "l"(b));
}
__device__ __forceinline__ void unpack2(unsigned long long v, float& lo, float& hi) {
    unsigned a, b;
    asm("mov.b64 {%0, %1}, %2;" : "=r"(a), "=r"(b) : "l"(v));
    lo = __uint_as_float(a);
    hi = __uint_as_float(b);
}

// ---------------- kernel 0: transpose conv weights to [c][tap][oc] ----------------
__global__ void k_transw(const float* __restrict__ mb_w) {
    int idx = blockIdx.x * 256 + threadIdx.x;
    if (idx < C_IN * 9 * MB_CH) {
        int oc = idx & 63;
        int rest = idx >> 6;
        int t = rest % 9;
        int c = rest / 9;
        g_tw[idx] = mb_w[oc * (C_IN * 9) + c * 9 + t];
    }
}

// ---------------- kernel 1: heatmap head (sigmoid + clip) ----------------
__global__ void k_hm(const float* __restrict__ out1,
                     const float* __restrict__ hm_w,
                     const float* __restrict__ hm_b) {
    int p = blockIdx.x * 256 + threadIdx.x;
    if (p >= HW_H) return;
    float s = hm_b[0];
    #pragma unroll 8
    for (int c = 0; c < C_IN; c++)
        s += hm_w[c] * out1[c * HW_H + p];
    float sg = 1.0f / (1.0f + expf(-s));
    sg = fminf(fmaxf(sg, 1e-4f), 1.0f - 1e-4f);
    g_hm[p] = sg;
}

// ---------------- top-k helpers ----------------
__device__ __forceinline__ bool tk_better(float v1, int i1, float v2, int i2) {
    return (v1 > v2) || (v1 == v2 && i1 < i2);
}

// merge two sorted-desc length-4 lists in shared memory (tree reduction step)
template <int NT>
__device__ __forceinline__ void tk_tree_merge(float* sv, int* si, int tid) {
    for (int stride = NT / 2; stride >= 1; stride >>= 1) {
        __syncthreads();
        if (tid < stride) {
            float av[4], cv[4], mv[4];
            int ai[4], ci[4], mi[4];
            #pragma unroll
            for (int j = 0; j < 4; j++) {
                av[j] = sv[tid * 4 + j];            ai[j] = si[tid * 4 + j];
                cv[j] = sv[(tid + stride) * 4 + j]; ci[j] = si[(tid + stride) * 4 + j];
            }
            int pa = 0, pb = 0;
            #pragma unroll
            for (int j = 0; j < 4; j++) {
                if (tk_better(av[pa], ai[pa], cv[pb], ci[pb])) { mv[j] = av[pa]; mi[j] = ai[pa]; pa++; }
                else                                          { mv[j] = cv[pb]; mi[j] = ci[pb]; pb++; }
            }
            #pragma unroll
            for (int j = 0; j < 4; j++) { sv[tid * 4 + j] = mv[j]; si[tid * 4 + j] = mi[j]; }
        }
    }
    __syncthreads();
}

// ---------------- kernel 2a: NMS + per-block top-4 (128 blocks x 256 thr) ----------------
__global__ void k_topk_part() {
    __shared__ float sv[256 * 4];
    __shared__ int   si[256 * 4];
    int tid = threadIdx.x;
    int p = blockIdx.x * 256 + tid;

    float heat = -1.0f;
    int   idx  = 0x7fffffff;
    if (p < HW_H) {
        int y = p / W_H, x = p % W_H;
        float v = g_hm[p];
        float mx = v;
        #pragma unroll
        for (int dy = -1; dy <= 1; dy++) {
            int yy = y + dy;
            if (yy < 0 || yy >= H_H) continue;
            #pragma unroll
            for (int dx = -1; dx <= 1; dx++) {
                int xx = x + dx;
                if (xx < 0 || xx >= W_H) continue;
                mx = fmaxf(mx, g_hm[yy * W_H + xx]);
            }
        }
        heat = (mx == v) ? v : 0.0f;
        idx = p;
    }
    sv[tid * 4 + 0] = heat; si[tid * 4 + 0] = idx;
    #pragma unroll
    for (int j = 1; j < 4; j++) { sv[tid * 4 + j] = -1.0f; si[tid * 4 + j] = 0x7fffffff; }

    tk_tree_merge<256>(sv, si, tid);

    if (tid < 4) {
        g_pv[blockIdx.x * 4 + tid] = sv[tid];
        g_pi[blockIdx.x * 4 + tid] = si[tid];
    }
}

// ---------------- kernel 2b: merge 128 partial lists -> global top-4 ----------------
__global__ void k_topk_merge(float* __restrict__ dout) {
    __shared__ float sv[128 * 4];
    __shared__ int   si[128 * 4];
    int tid = threadIdx.x;   // 128 threads
    #pragma unroll
    for (int j = 0; j < 4; j++) {
        sv[tid * 4 + j] = g_pv[tid * 4 + j];
        si[tid * 4 + j] = g_pi[tid * 4 + j];
    }
    tk_tree_merge<128>(sv, si, tid);
    if (tid < 4) {
        g_scores[tid] = sv[tid];
        g_inds[tid]   = si[tid];
        dout[OFF_SCORES + tid] = sv[tid];
        dout[OFF_INDS + tid]   = (float)si[tid];
    }
}

// ---------------- kernel 3: gen params at the 4 selected pixels (1 warp / output) ----------------
__global__ void k_genparams(const float* __restrict__ out1,
                            const float* __restrict__ params_w,
                            const float* __restrict__ params_b) {
    int w = blockIdx.x * 8 + (threadIdx.x >> 5);
    int lane = threadIdx.x & 31;
    if (w >= NUM_INS * NGP) return;
    int ins = w / NGP;
    int k = w % NGP;
    int p = g_inds[ins];
    const float4* pw = (const float4*)(params_w + k * C_IN);
    float s = 0.0f;
    #pragma unroll
    for (int j = 0; j < 2; j++) {
        float4 wv = pw[lane * 2 + j];
        int c0 = lane * 8 + j * 4;
        s += wv.x * out1[(c0 + 0) * HW_H + p];
        s += wv.y * out1[(c0 + 1) * HW_H + p];
        s += wv.z * out1[(c0 + 2) * HW_H + p];
        s += wv.w * out1[(c0 + 3) * HW_H + p];
    }
    #pragma unroll
    for (int o = 16; o >= 1; o >>= 1)
        s += __shfl_xor_sync(0xffffffffu, s, o);
    if (lane == 0) g_gp[w] = s + params_b[k];
}

// ---------------- kernel 4: fused 3x3 conv + relu + dynamic heads (packed f32x2) ----------------
__global__ __launch_bounds__(256, 2)
void k_conv_heads(const float* __restrict__ out0,
                  const float* __restrict__ mb_b,
                  float* __restrict__ dout) {
    __shared__ float s_in[2][18 * 18];
    __shared__ float s_w[2][9 * MB_CH];
    __shared__ float s_gp[NUM_INS * NGP];
    __shared__ float s_mb[MB_CH];

    int tid = threadIdx.x;
    int tx = tid & 15, ty = tid >> 4;
    int x0 = blockIdx.x * 16, y0 = blockIdx.y * 16;

    for (int i = tid; i < NUM_INS * NGP; i += 256) s_gp[i] = g_gp[i];
    if (tid < MB_CH) s_mb[tid] = mb_b[tid];

    // stage channel c into buffer buf
    auto stage = [&](int buf, int c) {
        for (int i = tid; i < 324; i += 256) {
            int r = i / 18, col = i % 18;
            int gy = y0 + r - 1, gx = x0 + col - 1;
            float v = 0.0f;
            if (gy >= 0 && gy < H_M && gx >= 0 && gx < W_M)
                v = out0[c * HW_M + gy * W_M + gx];
            s_in[buf][i] = v;
        }
        if (tid < 144)
            ((float4*)s_w[buf])[tid] = ((const float4*)(g_tw + c * 576))[tid];
    };

    unsigned long long acc2[32];
    #pragma unroll
    for (int i = 0; i < 32; i++) acc2[i] = 0ull;

    stage(0, 0);
    for (int c = 0; c < C_IN; c++) {
        __syncthreads();
        if (c + 1 < C_IN) stage((c + 1) & 1, c + 1);
        int b = c & 1;

        unsigned long long in2[9];
        #pragma unroll
        for (int dy = 0; dy < 3; dy++)
            #pragma unroll
            for (int dx = 0; dx < 3; dx++)
                in2[dy * 3 + dx] = pack2(s_in[b][(ty + dy) * 18 + tx + dx]);

        #pragma unroll
        for (int t = 0; t < 9; t++) {
            const ulonglong2* wp = (const ulonglong2*)(s_w[b] + t * MB_CH);
            unsigned long long iv = in2[t];
            #pragma unroll
            for (int q = 0; q < 16; q++) {
                ulonglong2 u = wp[q];
                fma2(acc2[2 * q + 0], iv, u.x);
                fma2(acc2[2 * q + 1], iv, u.y);
            }
        }
    }

    // unpack, bias + relu
    float acc[MB_CH];
    #pragma unroll
    for (int q = 0; q < 32; q++) {
        float lo, hi;
        unpack2(acc2[q], lo, hi);
        acc[2 * q + 0] = lo;
        acc[2 * q + 1] = hi;
    }
    #pragma unroll
    for (int i = 0; i < MB_CH; i++) acc[i] = fmaxf(acc[i] + s_mb[i], 0.0f);

    int gx = x0 + tx, gy = y0 + ty;
    float xx = -1.0f + 2.0f * (float)gx / (float)(W_M - 1);
    float yy = -1.0f + 2.0f * (float)gy / (float)(H_M - 1);
    int pix = gy * W_M + gx;

    #pragma unroll
    for (int ins = 0; ins < NUM_INS; ins++) {
        const float* gp = s_gp + ins * NGP;
        float m = gp[66] + gp[64] * xx + gp[65] * yy;
        float r = gp[133] + gp[NMP + 64] * xx + gp[NMP + 65] * yy;
        #pragma unroll
        for (int cc = 0; cc < MB_CH; cc++) {
            m += gp[cc] * acc[cc];
            r += gp[NMP + cc] * acc[cc];
        }
        dout[OFF_MASKS + ins * HW_M + pix] = m;
        dout[OFF_REGS  + ins * HW_M + pix] = r;
    }
}

// ---------------- kernel 5: per-column MLP over masks0 ----------------
__global__ void k_mlp(const float* __restrict__ w1, const float* __restrict__ b1,
                      const float* __restrict__ w2, const float* __restrict__ b2,
                      float* __restrict__ dout) {
    __shared__ float sh[4][HID];
    int tid = threadIdx.x;
    int lcol = tid / HID;      // 0..3
    int j = tid % HID;
    int g = blockIdx.x * 4 + lcol;   // 0..1919
    int ins = g / W_M;
    int x = g % W_M;
    const float* mbase = dout + OFF_MASKS + ins * HW_M + x;
    float s = b1[j];
    #pragma unroll 4
    for (int y = 0; y < H_M; y++)
        s += mbase[y * W_M] * w1[y * HID + j];
    sh[lcol][j] = fmaxf(s, 0.0f);
    __syncthreads();
    if (tid < 8) {
        int lc = tid >> 1, j2 = tid & 1;
        int gg = blockIdx.x * 4 + lc;
        float s2 = b2[j2];
        #pragma unroll
        for (int jj = 0; jj < HID; jj++)
            s2 += sh[lc][jj] * w2[jj * 2 + j2];
        dout[OFF_FEAT + gg * 2 + j2] = s2;
    }
}

// ---------------- launcher ----------------
extern "C" void kernel_launch(void* const* d_in, const int* in_sizes, int n_in,
                              void* d_out, int out_size) {
    const float* out0     = (const float*)d_in[0];
    const float* out1     = (const float*)d_in[1];
    const float* hm_w     = (const float*)d_in[2];
    const float* hm_b     = (const float*)d_in[3];
    const float* params_w = (const float*)d_in[4];
    const float* params_b = (const float*)d_in[5];
    const float* mb_w     = (const float*)d_in[6];
    const float* mb_b     = (const float*)d_in[7];
    const float* mlp_w1   = (const float*)d_in[8];
    const float* mlp_b1   = (const float*)d_in[9];
    const float* mlp_w2   = (const float*)d_in[10];
    const float* mlp_b2   = (const float*)d_in[11];
    float* dout = (float*)d_out;

    k_transw<<<(C_IN * 9 * MB_CH + 255) / 256, 256>>>(mb_w);
    k_hm<<<(HW_H + 255) / 256, 256>>>(out1, hm_w, hm_b);
    k_topk_part<<<128, 256>>>();
    k_topk_merge<<<1, 128>>>(dout);
    k_genparams<<<67, 256>>>(out1, params_w, params_b);
    dim3 cgrid(W_M / 16, H_M / 16);
    k_conv_heads<<<cgrid, 256>>>(out0, mb_b, dout);
    k_mlp<<<(NUM_INS * W_M) / 4, 256>>>(mlp_w1, mlp_b1, mlp_w2, mlp_b2, dout);
}

// round 3
// speedup vs baseline: 1.6711x; 1.3954x over previous
#include <cuda_runtime.h>
#include <cuda_bf16.h>
#include <math.h>

// ---------------- problem constants ----------------
#define C_IN     256
#define H_M      272
#define W_M      480
#define HW_M     (H_M * W_M)          // 130560
#define H_H      136
#define W_H      240
#define HW_H     (H_H * W_H)          // 32640
#define MB_CH    64
#define NUM_INS  4
#define NGP      134
#define NMP      67
#define HID      64

#define OFF_SCORES 0
#define OFF_INDS   4
#define OFF_REGS   8
#define OFF_MASKS  (8 + NUM_INS * HW_M)
#define OFF_FEAT   (OFF_MASKS + NUM_INS * HW_M)

// ---------------- device scratch ----------------
__device__ float g_hm[HW_H];
__device__ float g_scores[NUM_INS];
__device__ int   g_inds[NUM_INS];
__device__ float g_gp[NUM_INS * NGP];
__device__ float g_tw[C_IN * 9 * MB_CH];   // [c][tap][oc]
__device__ float g_pv[128 * 4];
__device__ int   g_pi[128 * 4];

// ---------------- packed f32x2 helpers ----------------
__device__ __forceinline__ unsigned long long pack2(float v) {
    unsigned long long r;
    unsigned u = __float_as_uint(v);
    asm("mov.b64 %0, {%1, %1};" : "=l"(r) : "r"(u));
    return r;
}
__device__ __forceinline__ void fma2(unsigned long long& d,
                                     unsigned long long a,
                                     unsigned long long b) {
    asm("fma.rn.f32x2 %0, %1, %2, %0;" : "+l"(d) : "l"(a), "l"(b));
}
__device__ __forceinline__ void unpack2(unsigned long long v, float& lo, float& hi) {
    unsigned a, b;
    asm("mov.b64 {%0, %1}, %2;" : "=r"(a), "=r"(b) : "l"(v));
    lo = __uint_as_float(a);
    hi = __uint_as_float(b);
}

// ---------------- kernel 0: transpose conv weights ----------------
__global__ void k_transw(const float* __restrict__ mb_w) {
    int idx = blockIdx.x * 256 + threadIdx.x;
    if (idx < C_IN * 9 * MB_CH) {
        int oc = idx & 63;
        int rest = idx >> 6;
        int t = rest % 9;
        int c = rest / 9;
        g_tw[idx] = mb_w[oc * (C_IN * 9) + c * 9 + t];
    }
}

// ---------------- kernel 1: heatmap head ----------------
__global__ void k_hm(const float* __restrict__ out1,
                     const float* __restrict__ hm_w,
                     const float* __restrict__ hm_b) {
    int p = blockIdx.x * 256 + threadIdx.x;
    if (p >= HW_H) return;
    float s = hm_b[0];
    #pragma unroll 8
    for (int c = 0; c < C_IN; c++)
        s += hm_w[c] * out1[c * HW_H + p];
    float sg = 1.0f / (1.0f + expf(-s));
    sg = fminf(fmaxf(sg, 1e-4f), 1.0f - 1e-4f);
    g_hm[p] = sg;
}

// ---------------- top-k ----------------
__device__ __forceinline__ bool tk_better(float v1, int i1, float v2, int i2) {
    return (v1 > v2) || (v1 == v2 && i1 < i2);
}

template <int NT>
__device__ __forceinline__ void tk_tree_merge(float* sv, int* si, int tid) {
    for (int stride = NT / 2; stride >= 1; stride >>= 1) {
        __syncthreads();
        if (tid < stride) {
            float av[4], cv[4], mv[4];
            int ai[4], ci[4], mi[4];
            #pragma unroll
            for (int j = 0; j < 4; j++) {
                av[j] = sv[tid * 4 + j];            ai[j] = si[tid * 4 + j];
                cv[j] = sv[(tid + stride) * 4 + j]; ci[j] = si[(tid + stride) * 4 + j];
            }
            int pa = 0, pb = 0;
            #pragma unroll
            for (int j = 0; j < 4; j++) {
                if (tk_better(av[pa], ai[pa], cv[pb], ci[pb])) { mv[j] = av[pa]; mi[j] = ai[pa]; pa++; }
                else                                          { mv[j] = cv[pb]; mi[j] = ci[pb]; pb++; }
            }
            #pragma unroll
            for (int j = 0; j < 4; j++) { sv[tid * 4 + j] = mv[j]; si[tid * 4 + j] = mi[j]; }
        }
    }
    __syncthreads();
}

__global__ void k_topk_part() {
    __shared__ float sv[256 * 4];
    __shared__ int   si[256 * 4];
    int tid = threadIdx.x;
    int p = blockIdx.x * 256 + tid;

    float heat = -1.0f;
    int   idx  = 0x7fffffff;
    if (p < HW_H) {
        int y = p / W_H, x = p % W_H;
        float v = g_hm[p];
        float mx = v;
        #pragma unroll
        for (int dy = -1; dy <= 1; dy++) {
            int yy = y + dy;
            if (yy < 0 || yy >= H_H) continue;
            #pragma unroll
            for (int dx = -1; dx <= 1; dx++) {
                int xx = x + dx;
                if (xx < 0 || xx >= W_H) continue;
                mx = fmaxf(mx, g_hm[yy * W_H + xx]);
            }
        }
        heat = (mx == v) ? v : 0.0f;
        idx = p;
    }
    sv[tid * 4 + 0] = heat; si[tid * 4 + 0] = idx;
    #pragma unroll
    for (int j = 1; j < 4; j++) { sv[tid * 4 + j] = -1.0f; si[tid * 4 + j] = 0x7fffffff; }

    tk_tree_merge<256>(sv, si, tid);

    if (tid < 4) {
        g_pv[blockIdx.x * 4 + tid] = sv[tid];
        g_pi[blockIdx.x * 4 + tid] = si[tid];
    }
}

__global__ void k_topk_merge(float* __restrict__ dout) {
    __shared__ float sv[128 * 4];
    __shared__ int   si[128 * 4];
    int tid = threadIdx.x;
    #pragma unroll
    for (int j = 0; j < 4; j++) {
        sv[tid * 4 + j] = g_pv[tid * 4 + j];
        si[tid * 4 + j] = g_pi[tid * 4 + j];
    }
    tk_tree_merge<128>(sv, si, tid);
    if (tid < 4) {
        g_scores[tid] = sv[tid];
        g_inds[tid]   = si[tid];
        dout[OFF_SCORES + tid] = sv[tid];
        dout[OFF_INDS + tid]   = (float)si[tid];
    }
}

// ---------------- kernel 3: gen params at the 4 pixels ----------------
__global__ void k_genparams(const float* __restrict__ out1,
                            const float* __restrict__ params_w,
                            const float* __restrict__ params_b) {
    int w = blockIdx.x * 8 + (threadIdx.x >> 5);
    int lane = threadIdx.x & 31;
    if (w >= NUM_INS * NGP) return;
    int ins = w / NGP;
    int k = w % NGP;
    int p = g_inds[ins];
    const float4* pw = (const float4*)(params_w + k * C_IN);
    float s = 0.0f;
    #pragma unroll
    for (int j = 0; j < 2; j++) {
        float4 wv = pw[lane * 2 + j];
        int c0 = lane * 8 + j * 4;
        s += wv.x * out1[(c0 + 0) * HW_H + p];
        s += wv.y * out1[(c0 + 1) * HW_H + p];
        s += wv.z * out1[(c0 + 2) * HW_H + p];
        s += wv.w * out1[(c0 + 3) * HW_H + p];
    }
    #pragma unroll
    for (int o = 16; o >= 1; o >>= 1)
        s += __shfl_xor_sync(0xffffffffu, s, o);
    if (lane == 0) g_gp[w] = s + params_b[k];
}

// ---------------- kernel 4: fused conv + relu + heads ----------------
// thread layout: ocg = tid>>6 (4 oc-groups of 16), g = tid&63 (pixel groups)
// pixel group g: row r = g>>2, cols xq..xq+3 where xq = (g&3)*4
// each thread: 4 pixels x 16 oc, accumulators packed f32x2 over oc pairs.
__global__ __launch_bounds__(256, 2)
void k_conv_heads(const float* __restrict__ out0,
                  const float* __restrict__ mb_b,
                  float* __restrict__ dout) {
    __shared__ float s_in[2][18 * 18];
    __shared__ float s_w[2][9 * MB_CH];
    __shared__ float s_gp[NUM_INS * NGP];
    __shared__ float s_mb[MB_CH];
    __shared__ float s_part[64][4][4][8];   // [g][pixj][ocg][m0..3, r0..3]

    int tid = threadIdx.x;
    int ocg = tid >> 6;
    int g = tid & 63;
    int r = g >> 2;
    int xq = (g & 3) << 2;
    int x0 = blockIdx.x * 16, y0 = blockIdx.y * 16;

    for (int i = tid; i < NUM_INS * NGP; i += 256) s_gp[i] = g_gp[i];
    if (tid < MB_CH) s_mb[tid] = mb_b[tid];

    auto stage = [&](int buf, int c) {
        for (int i = tid; i < 324; i += 256) {
            int rr = i / 18, col = i % 18;
            int gy = y0 + rr - 1, gx = x0 + col - 1;
            float v = 0.0f;
            if (gy >= 0 && gy < H_M && gx >= 0 && gx < W_M)
                v = out0[c * HW_M + gy * W_M + gx];
            s_in[buf][i] = v;
        }
        if (tid < 144)
            ((float4*)s_w[buf])[tid] = ((const float4*)(g_tw + c * 576))[tid];
    };

    unsigned long long acc2[4][8];
    #pragma unroll
    for (int j = 0; j < 4; j++)
        #pragma unroll
        for (int q = 0; q < 8; q++) acc2[j][q] = 0ull;

    stage(0, 0);
    for (int c = 0; c < C_IN; c++) {
        __syncthreads();
        if (c + 1 < C_IN) stage((c + 1) & 1, c + 1);
        int b = c & 1;
        const float* Sin = s_in[b];
        const float* Sw = s_w[b];

        #pragma unroll
        for (int dy = 0; dy < 3; dy++) {
            const float* rowp = Sin + (r + dy) * 18 + xq;
            unsigned long long sp[6];
            #pragma unroll
            for (int i = 0; i < 6; i++) sp[i] = pack2(rowp[i]);

            #pragma unroll
            for (int dx = 0; dx < 3; dx++) {
                const ulonglong2* wp =
                    (const ulonglong2*)(Sw + ((dy * 3 + dx) << 6) + (ocg << 4));
                ulonglong2 w0 = wp[0], w1 = wp[1], w2 = wp[2], w3 = wp[3];
                #pragma unroll
                for (int j = 0; j < 4; j++) {
                    unsigned long long s = sp[j + dx];
                    fma2(acc2[j][0], s, w0.x); fma2(acc2[j][1], s, w0.y);
                    fma2(acc2[j][2], s, w1.x); fma2(acc2[j][3], s, w1.y);
                    fma2(acc2[j][4], s, w2.x); fma2(acc2[j][5], s, w2.y);
                    fma2(acc2[j][6], s, w3.x); fma2(acc2[j][7], s, w3.y);
                }
            }
        }
    }

    // bias + relu + partial head dots (16 oc per thread)
    #pragma unroll
    for (int j = 0; j < 4; j++) {
        float f[16];
        #pragma unroll
        for (int q = 0; q < 8; q++) {
            float a0, a1;
            unpack2(acc2[j][q], a0, a1);
            f[2 * q + 0] = fmaxf(a0 + s_mb[ocg * 16 + 2 * q + 0], 0.0f);
            f[2 * q + 1] = fmaxf(a1 + s_mb[ocg * 16 + 2 * q + 1], 0.0f);
        }
        #pragma unroll
        for (int ins = 0; ins < NUM_INS; ins++) {
            const float* gp = s_gp + ins * NGP;
            float m = 0.0f, rr = 0.0f;
            #pragma unroll
            for (int k = 0; k < 16; k++) {
                m  += gp[ocg * 16 + k] * f[k];
                rr += gp[NMP + ocg * 16 + k] * f[k];
            }
            s_part[g][j][ocg][ins]     = m;
            s_part[g][j][ocg][4 + ins] = rr;
        }
    }
    __syncthreads();

    // final reduce over the 4 oc-groups; one pixel per thread
    int pr = tid >> 4, pc = tid & 15;
    int g2 = pr * 4 + (pc >> 2), j2 = pc & 3;
    int gx = x0 + pc, gy = y0 + pr;
    float xx = -1.0f + 2.0f * (float)gx / (float)(W_M - 1);
    float yy = -1.0f + 2.0f * (float)gy / (float)(H_M - 1);
    int pix = gy * W_M + gx;

    #pragma unroll
    for (int ins = 0; ins < NUM_INS; ins++) {
        const float* gp = s_gp + ins * NGP;
        float m  = gp[66]  + gp[64] * xx + gp[65] * yy;
        float rr = gp[133] + gp[NMP + 64] * xx + gp[NMP + 65] * yy;
        #pragma unroll
        for (int og = 0; og < 4; og++) {
            m  += s_part[g2][j2][og][ins];
            rr += s_part[g2][j2][og][4 + ins];
        }
        dout[OFF_MASKS + ins * HW_M + pix] = m;
        dout[OFF_REGS  + ins * HW_M + pix] = rr;
    }
}

// ---------------- kernel 5: per-column MLP over masks0 ----------------
__global__ void k_mlp(const float* __restrict__ w1, const float* __restrict__ b1,
                      const float* __restrict__ w2, const float* __restrict__ b2,
                      float* __restrict__ dout) {
    __shared__ float sh[4][HID];
    int tid = threadIdx.x;
    int lcol = tid / HID;
    int j = tid % HID;
    int g = blockIdx.x * 4 + lcol;
    int ins = g / W_M;
    int x = g % W_M;
    const float* mbase = dout + OFF_MASKS + ins * HW_M + x;
    float s = b1[j];
    #pragma unroll 4
    for (int y = 0; y < H_M; y++)
        s += mbase[y * W_M] * w1[y * HID + j];
    sh[lcol][j] = fmaxf(s, 0.0f);
    __syncthreads();
    if (tid < 8) {
        int lc = tid >> 1, j2 = tid & 1;
        int gg = blockIdx.x * 4 + lc;
        float s2 = b2[j2];
        #pragma unroll
        for (int jj = 0; jj < HID; jj++)
            s2 += sh[lc][jj] * w2[jj * 2 + j2];
        dout[OFF_FEAT + gg * 2 + j2] = s2;
    }
}

// ---------------- launcher ----------------
extern "C" void kernel_launch(void* const* d_in, const int* in_sizes, int n_in,
                              void* d_out, int out_size) {
    const float* out0     = (const float*)d_in[0];
    const float* out1     = (const float*)d_in[1];
    const float* hm_w     = (const float*)d_in[2];
    const float* hm_b     = (const float*)d_in[3];
    const float* params_w = (const float*)d_in[4];
    const float* params_b = (const float*)d_in[5];
    const float* mb_w     = (const float*)d_in[6];
    const float* mb_b     = (const float*)d_in[7];
    const float* mlp_w1   = (const float*)d_in[8];
    const float* mlp_b1   = (const float*)d_in[9];
    const float* mlp_w2   = (const float*)d_in[10];
    const float* mlp_b2   = (const float*)d_in[11];
    float* dout = (float*)d_out;

    k_transw<<<(C_IN * 9 * MB_CH + 255) / 256, 256>>>(mb_w);
    k_hm<<<(HW_H + 255) / 256, 256>>>(out1, hm_w, hm_b);
    k_topk_part<<<128, 256>>>();
    k_topk_merge<<<1, 128>>>(dout);
    k_genparams<<<67, 256>>>(out1, params_w, params_b);
    dim3 cgrid(W_M / 16, H_M / 16);
    k_conv_heads<<<cgrid, 256>>>(out0, mb_b, dout);
    k_mlp<<<(NUM_INS * W_M) / 4, 256>>>(mlp_w1, mlp_b1, mlp_w2, mlp_b2, dout);
}

// round 5
// speedup vs baseline: 3.8793x; 2.3214x over previous
#include <cuda_runtime.h>
#include <cuda_bf16.h>
#include <math.h>
#include <stdint.h>

// ---------------- problem constants ----------------
#define C_IN     256
#define H_M      272
#define W_M      480
#define HW_M     (H_M * W_M)          // 130560
#define H_H      136
#define W_H      240
#define HW_H     (H_H * W_H)          // 32640
#define MB_CH    64
#define NUM_INS  4
#define NGP      134
#define NMP      67
#define HID      64

#define OFF_SCORES 0
#define OFF_INDS   4
#define OFF_REGS   8
#define OFF_MASKS  (8 + NUM_INS * HW_M)
#define OFF_FEAT   (OFF_MASKS + NUM_INS * HW_M)

// ---------------- device scratch ----------------
__device__ float g_hm[HW_H];
__device__ float g_scores[NUM_INS];
__device__ int   g_inds[NUM_INS];
__device__ float g_gp[NUM_INS * NGP];
__device__ float g_pv[128 * 4];
__device__ int   g_pi[128 * 4];
// split conv weights, layout [tap][oc][c] bf16
__device__ __nv_bfloat16 g_twh[9 * MB_CH * C_IN];
__device__ __nv_bfloat16 g_twl[9 * MB_CH * C_IN];

// ---------------- helpers ----------------
__device__ __forceinline__ uint32_t smem_u32(const void* p) {
    uint32_t a;
    asm("{ .reg .u64 t; cvta.to.shared.u64 t, %1; cvt.u32.u64 %0, t; }"
        : "=r"(a) : "l"(p));
    return a;
}

__device__ __forceinline__ void mma_bf16(float* c, const uint32_t* a, const uint32_t* b) {
    asm volatile(
        "mma.sync.aligned.m16n8k16.row.col.f32.bf16.bf16.f32 "
        "{%0,%1,%2,%3}, {%4,%5,%6,%7}, {%8,%9}, {%0,%1,%2,%3};"
        : "+f"(c[0]), "+f"(c[1]), "+f"(c[2]), "+f"(c[3])
        : "r"(a[0]), "r"(a[1]), "r"(a[2]), "r"(a[3]), "r"(b[0]), "r"(b[1]));
}

__device__ __forceinline__ void ldsm4(uint32_t* r, uint32_t addr) {
    asm volatile("ldmatrix.sync.aligned.m8n8.x4.shared.b16 {%0,%1,%2,%3}, [%4];"
        : "=r"(r[0]), "=r"(r[1]), "=r"(r[2]), "=r"(r[3]) : "r"(addr));
}

// ---------------- kernel 0: split conv weights to bf16 hi/lo, [tap][oc][c] ----------------
__global__ void k_prepw(const float* __restrict__ mb_w) {
    int idx = blockIdx.x * 256 + threadIdx.x;
    if (idx >= 9 * MB_CH * C_IN) return;
    int t = idx / (MB_CH * C_IN);
    int rem = idx % (MB_CH * C_IN);
    int oc = rem >> 8;
    int c = rem & 255;
    float w = mb_w[oc * (C_IN * 9) + c * 9 + t];
    __nv_bfloat16 hi = __float2bfloat16_rn(w);
    __nv_bfloat16 lo = __float2bfloat16_rn(w - __bfloat162float(hi));
    g_twh[idx] = hi;
    g_twl[idx] = lo;
}

// ---------------- kernel 1: heatmap head ----------------
__global__ void k_hm(const float* __restrict__ out1,
                     const float* __restrict__ hm_w,
                     const float* __restrict__ hm_b) {
    int p = blockIdx.x * 256 + threadIdx.x;
    if (p >= HW_H) return;
    float s = hm_b[0];
    #pragma unroll 8
    for (int c = 0; c < C_IN; c++)
        s += hm_w[c] * out1[c * HW_H + p];
    float sg = 1.0f / (1.0f + expf(-s));
    sg = fminf(fmaxf(sg, 1e-4f), 1.0f - 1e-4f);
    g_hm[p] = sg;
}

// ---------------- top-k ----------------
__device__ __forceinline__ bool tk_better(float v1, int i1, float v2, int i2) {
    return (v1 > v2) || (v1 == v2 && i1 < i2);
}

template <int NT>
__device__ __forceinline__ void tk_tree_merge(float* sv, int* si, int tid) {
    for (int stride = NT / 2; stride >= 1; stride >>= 1) {
        __syncthreads();
        if (tid < stride) {
            float av[4], cv[4], mv[4];
            int ai[4], ci[4], mi[4];
            #pragma unroll
            for (int j = 0; j < 4; j++) {
                av[j] = sv[tid * 4 + j];            ai[j] = si[tid * 4 + j];
                cv[j] = sv[(tid + stride) * 4 + j]; ci[j] = si[(tid + stride) * 4 + j];
            }
            int pa = 0, pb = 0;
            #pragma unroll
            for (int j = 0; j < 4; j++) {
                if (tk_better(av[pa], ai[pa], cv[pb], ci[pb])) { mv[j] = av[pa]; mi[j] = ai[pa]; pa++; }
                else                                          { mv[j] = cv[pb]; mi[j] = ci[pb]; pb++; }
            }
            #pragma unroll
            for (int j = 0; j < 4; j++) { sv[tid * 4 + j] = mv[j]; si[tid * 4 + j] = mi[j]; }
        }
    }
    __syncthreads();
}

__global__ void k_topk_part() {
    __shared__ float sv[256 * 4];
    __shared__ int   si[256 * 4];
    int tid = threadIdx.x;
    int p = blockIdx.x * 256 + tid;

    float heat = -1.0f;
    int   idx  = 0x7fffffff;
    if (p < HW_H) {
        int y = p / W_H, x = p % W_H;
        float v = g_hm[p];
        float mx = v;
        #pragma unroll
        for (int dy = -1; dy <= 1; dy++) {
            int yy = y + dy;
            if (yy < 0 || yy >= H_H) continue;
            #pragma unroll
            for (int dx = -1; dx <= 1; dx++) {
                int xx = x + dx;
                if (xx < 0 || xx >= W_H) continue;
                mx = fmaxf(mx, g_hm[yy * W_H + xx]);
            }
        }
        heat = (mx == v) ? v : 0.0f;
        idx = p;
    }
    sv[tid * 4 + 0] = heat; si[tid * 4 + 0] = idx;
    #pragma unroll
    for (int j = 1; j < 4; j++) { sv[tid * 4 + j] = -1.0f; si[tid * 4 + j] = 0x7fffffff; }

    tk_tree_merge<256>(sv, si, tid);

    if (tid < 4) {
        g_pv[blockIdx.x * 4 + tid] = sv[tid];
        g_pi[blockIdx.x * 4 + tid] = si[tid];
    }
}

__global__ void k_topk_merge(float* __restrict__ dout) {
    __shared__ float sv[128 * 4];
    __shared__ int   si[128 * 4];
    int tid = threadIdx.x;
    #pragma unroll
    for (int j = 0; j < 4; j++) {
        sv[tid * 4 + j] = g_pv[tid * 4 + j];
        si[tid * 4 + j] = g_pi[tid * 4 + j];
    }
    tk_tree_merge<128>(sv, si, tid);
    if (tid < 4) {
        g_scores[tid] = sv[tid];
        g_inds[tid]   = si[tid];
        dout[OFF_SCORES + tid] = sv[tid];
        dout[OFF_INDS + tid]   = (float)si[tid];
    }
}

// ---------------- kernel 3: gen params at the 4 pixels ----------------
__global__ void k_genparams(const float* __restrict__ out1,
                            const float* __restrict__ params_w,
                            const float* __restrict__ params_b) {
    int w = blockIdx.x * 8 + (threadIdx.x >> 5);
    int lane = threadIdx.x & 31;
    if (w >= NUM_INS * NGP) return;
    int ins = w / NGP;
    int k = w % NGP;
    int p = g_inds[ins];
    const float4* pw = (const float4*)(params_w + k * C_IN);
    float s = 0.0f;
    #pragma unroll
    for (int j = 0; j < 2; j++) {
        float4 wv = pw[lane * 2 + j];
        int c0 = lane * 8 + j * 4;
        s += wv.x * out1[(c0 + 0) * HW_H + p];
        s += wv.y * out1[(c0 + 1) * HW_H + p];
        s += wv.z * out1[(c0 + 2) * HW_H + p];
        s += wv.w * out1[(c0 + 3) * HW_H + p];
    }
    #pragma unroll
    for (int o = 16; o >= 1; o >>= 1)
        s += __shfl_xor_sync(0xffffffffu, s, o);
    if (lane == 0) g_gp[w] = s + params_b[k];
}

// ---------------- kernel 4: mma.sync split-bf16 conv + relu + dynamic heads ----------------
// Per CTA: M=128 pixels (4 rows x 32 cols), N=64 oc, K=2304 (9 taps x 256 c).
// Warp grid 4(M) x 2(N); warp tile 32x32; fragments m16n8k16, fp32 acc in regs.
// Split: acc += Ah*Bh + Ah*Bl + Al*Bh.
// dynamic smem (bytes):
//   [0:2144)      s_gp (536 f)
//   [2144:2400)   s_mb (64 f)
//   [2432:57920)  halo: 204 pixels x 68 u32 (u32[0:32) = hi pairs, [32:64) = lo pairs)
//                 (aliased after mainloop as s_f: 128 x 65 floats)
//   [57920:76352) B tiles: hi 64x72 bf16 (144B rows), then lo
#define CONV_SMEM_BYTES 76416

__global__ __launch_bounds__(256, 2)
void k_conv_heads(const float* __restrict__ out0,
                  const float* __restrict__ mb_b,
                  float* __restrict__ dout) {
    extern __shared__ char smem[];
    uint32_t sb = smem_u32(smem);
    float* s_gp = (float*)smem;
    float* s_mb = (float*)(smem + 2144);
    uint32_t* s_halo = (uint32_t*)(smem + 2432);
    float* s_f = (float*)(smem + 2432);
    char* s_bh = smem + 57920;
    char* s_bl = smem + 57920 + 9216;
    uint32_t halo_base = sb + 2432;
    uint32_t b_base = sb + 57920;

    int tid = threadIdx.x;
    int lane = tid & 31;
    int wid = tid >> 5;
    int wm = wid & 3, wn = wid >> 2;
    int x0 = blockIdx.x * 32, y0 = blockIdx.y * 4;

    for (int i = tid; i < NUM_INS * NGP; i += 256) s_gp[i] = g_gp[i];
    if (tid < MB_CH) s_mb[tid] = mb_b[tid];

    // halo staging coords
    int hp_py = y0 - 1 + tid / 34;
    int hp_px = x0 - 1 + tid % 34;
    bool hp_in = (tid < 204) && (hp_py >= 0) && (hp_py < H_M) &&
                 (hp_px >= 0) && (hp_px < W_M);
    const float* hp_base = out0 + hp_py * W_M + hp_px;

    // per-lane ldmatrix offsets
    uint32_t a_lane = (uint32_t)((lane & 15) * 272 + (lane >> 4) * 16);
    uint32_t b_lane = (uint32_t)((((lane & 7) + ((lane >> 4) & 1) * 8) * 144) +
                                 ((lane >> 3) & 1) * 16);

    float acc[2][4][4];
    #pragma unroll
    for (int i = 0; i < 2; i++)
        #pragma unroll
        for (int j = 0; j < 4; j++)
            #pragma unroll
            for (int q = 0; q < 4; q++) acc[i][j][q] = 0.0f;

    for (int chunk = 0; chunk < 4; chunk++) {
        int c0 = chunk * 64;
        __syncthreads();   // previous chunk's compute done before halo overwrite
        if (tid < 204) {
            uint32_t* hrow = s_halo + tid * 68;
            #pragma unroll 4
            for (int j = 0; j < 32; j++) {
                int c = c0 + 2 * j;
                float v0 = hp_in ? hp_base[(size_t)c * HW_M] : 0.0f;
                float v1 = hp_in ? hp_base[(size_t)(c + 1) * HW_M] : 0.0f;
                __nv_bfloat16 h0 = __float2bfloat16_rn(v0);
                __nv_bfloat16 h1 = __float2bfloat16_rn(v1);
                __nv_bfloat16 l0 = __float2bfloat16_rn(v0 - __bfloat162float(h0));
                __nv_bfloat16 l1 = __float2bfloat16_rn(v1 - __bfloat162float(h1));
                hrow[j] = (uint32_t)__bfloat16_as_ushort(h0) |
                          ((uint32_t)__bfloat16_as_ushort(h1) << 16);
                hrow[32 + j] = (uint32_t)__bfloat16_as_ushort(l0) |
                               ((uint32_t)__bfloat16_as_ushort(l1) << 16);
            }
        }

        for (int t = 0; t < 9; t++) {
            __syncthreads();   // prev tap compute done (and halo ready at t==0)
            // stage B tile (hi + lo) for this (tap, chunk): 64 oc x 64 c, 144B rows
            {
                const __nv_bfloat16* srch = g_twh + t * (MB_CH * C_IN) + c0;
                const __nv_bfloat16* srcl = g_twl + t * (MB_CH * C_IN) + c0;
                #pragma unroll
                for (int q = 0; q < 4; q++) {
                    int v = tid + q * 256;
                    int tile = v >> 9;
                    int ii = v & 511;
                    int oc = ii >> 3, cg = ii & 7;
                    const __nv_bfloat16* src = (tile ? srcl : srch) + oc * C_IN + cg * 8;
                    char* dst = (tile ? s_bl : s_bh) + oc * 144 + cg * 16;
                    *(uint4*)dst = *(const uint4*)src;
                }
            }
            __syncthreads();

            int dy = t / 3, dx = t % 3;
            uint32_t a_row = halo_base +
                (uint32_t)(((wm + dy) * 34 + dx) * 272) + a_lane;
            uint32_t b_row = b_base + (uint32_t)(wn * 32 * 144) + b_lane;

            #pragma unroll
            for (int kb = 0; kb < 4; kb++) {
                uint32_t bh[4][2], bl[4][2];
                #pragma unroll
                for (int jj = 0; jj < 2; jj++) {
                    uint32_t ba = b_row + jj * (16 * 144) + kb * 32;
                    uint32_t r[4];
                    ldsm4(r, ba);
                    bh[jj * 2][0] = r[0]; bh[jj * 2][1] = r[1];
                    bh[jj * 2 + 1][0] = r[2]; bh[jj * 2 + 1][1] = r[3];
                    ldsm4(r, ba + 9216);
                    bl[jj * 2][0] = r[0]; bl[jj * 2][1] = r[1];
                    bl[jj * 2 + 1][0] = r[2]; bl[jj * 2 + 1][1] = r[3];
                }
                #pragma unroll
                for (int i = 0; i < 2; i++) {
                    uint32_t aa = a_row + i * (16 * 272) + kb * 32;
                    uint32_t ah[4], al[4];
                    ldsm4(ah, aa);
                    ldsm4(al, aa + 128);
                    #pragma unroll
                    for (int j = 0; j < 4; j++) {
                        mma_bf16(acc[i][j], ah, bh[j]);
                        mma_bf16(acc[i][j], ah, bl[j]);
                        mma_bf16(acc[i][j], al, bh[j]);
                    }
                }
            }
        }
    }

    // ---- epilogue: bias + relu into s_f (aliases halo), then dynamic heads ----
    __syncthreads();
    {
        int mrow = wm * 32 + (lane >> 2);
        int ocb = wn * 32 + (lane & 3) * 2;
        #pragma unroll
        for (int i = 0; i < 2; i++)
            #pragma unroll
            for (int j = 0; j < 4; j++) {
                int m = mrow + i * 16;
                int oc = ocb + j * 8;
                s_f[m * 65 + oc]           = fmaxf(acc[i][j][0] + s_mb[oc], 0.0f);
                s_f[m * 65 + oc + 1]       = fmaxf(acc[i][j][1] + s_mb[oc + 1], 0.0f);
                s_f[(m + 8) * 65 + oc]     = fmaxf(acc[i][j][2] + s_mb[oc], 0.0f);
                s_f[(m + 8) * 65 + oc + 1] = fmaxf(acc[i][j][3] + s_mb[oc + 1], 0.0f);
            }
    }
    __syncthreads();

    if (tid < 128) {
        float f[64];
        #pragma unroll
        for (int k = 0; k < 64; k++) f[k] = s_f[tid * 65 + k];

        int ar = tid >> 5, ax = tid & 31;
        int gx = x0 + ax, gy = y0 + ar;
        float xx = -1.0f + 2.0f * (float)gx / (float)(W_M - 1);
        float yy = -1.0f + 2.0f * (float)gy / (float)(H_M - 1);
        int pix = gy * W_M + gx;

        #pragma unroll
        for (int ins = 0; ins < NUM_INS; ins++) {
            const float* gp = s_gp + ins * NGP;
            float m  = gp[66]  + gp[64] * xx + gp[65] * yy;
            float rr = gp[133] + gp[NMP + 64] * xx + gp[NMP + 65] * yy;
            #pragma unroll
            for (int k = 0; k < 64; k++) {
                m  += gp[k] * f[k];
                rr += gp[NMP + k] * f[k];
            }
            dout[OFF_MASKS + ins * HW_M + pix] = m;
            dout[OFF_REGS  + ins * HW_M + pix] = rr;
        }
    }
}

// ---------------- kernel 5: per-column MLP over masks0 ----------------
__global__ void k_mlp(const float* __restrict__ w1, const float* __restrict__ b1,
                      const float* __restrict__ w2, const float* __restrict__ b2,
                      float* __restrict__ dout) {
    __shared__ float sh[4][HID];
    int tid = threadIdx.x;
    int lcol = tid / HID;
    int j = tid % HID;
    int g = blockIdx.x * 4 + lcol;
    int ins = g / W_M;
    int x = g % W_M;
    const float* mbase = dout + OFF_MASKS + ins * HW_M + x;
    float s = b1[j];
    #pragma unroll 4
    for (int y = 0; y < H_M; y++)
        s += mbase[y * W_M] * w1[y * HID + j];
    sh[lcol][j] = fmaxf(s, 0.0f);
    __syncthreads();
    if (tid < 8) {
        int lc = tid >> 1, j2 = tid & 1;
        int gg = blockIdx.x * 4 + lc;
        float s2 = b2[j2];
        #pragma unroll
        for (int jj = 0; jj < HID; jj++)
            s2 += sh[lc][jj] * w2[jj * 2 + j2];
        dout[OFF_FEAT + gg * 2 + j2] = s2;
    }
}

// ---------------- launcher ----------------
extern "C" void kernel_launch(void* const* d_in, const int* in_sizes, int n_in,
                              void* d_out, int out_size) {
    const float* out0     = (const float*)d_in[0];
    const float* out1     = (const float*)d_in[1];
    const float* hm_w     = (const float*)d_in[2];
    const float* hm_b     = (const float*)d_in[3];
    const float* params_w = (const float*)d_in[4];
    const float* params_b = (const float*)d_in[5];
    const float* mb_w     = (const float*)d_in[6];
    const float* mb_b     = (const float*)d_in[7];
    const float* mlp_w1   = (const float*)d_in[8];
    const float* mlp_b1   = (const float*)d_in[9];
    const float* mlp_w2   = (const float*)d_in[10];
    const float* mlp_b2   = (const float*)d_in[11];
    float* dout = (float*)d_out;

    cudaFuncSetAttribute(k_conv_heads,
                         cudaFuncAttributeMaxDynamicSharedMemorySize,
                         CONV_SMEM_BYTES);

    k_prepw<<<(9 * MB_CH * C_IN + 255) / 256, 256>>>(mb_w);
    k_hm<<<(HW_H + 255) / 256, 256>>>(out1, hm_w, hm_b);
    k_topk_part<<<128, 256>>>();
    k_topk_merge<<<1, 128>>>(dout);
    k_genparams<<<67, 256>>>(out1, params_w, params_b);
    dim3 cgrid(W_M / 32, H_M / 4);
    k_conv_heads<<<cgrid, 256, CONV_SMEM_BYTES>>>(out0, mb_b, dout);
    k_mlp<<<(NUM_INS * W_M) / 4, 256>>>(mlp_w1, mlp_b1, mlp_w2, mlp_b2, dout);
}

// round 7
// speedup vs baseline: 5.9669x; 1.5381x over previous
#include <cuda_runtime.h>
#include <cuda_bf16.h>
#include <cuda_fp16.h>
#include <math.h>
#include <stdint.h>

// ---------------- problem constants ----------------
#define C_IN     256
#define H_M      272
#define W_M      480
#define HW_M     (H_M * W_M)          // 130560
#define H_H      136
#define W_H      240
#define HW_H     (H_H * W_H)          // 32640
#define MB_CH    64
#define NUM_INS  4
#define NGP      134
#define NMP      67
#define HID      64

#define OFF_SCORES 0
#define OFF_INDS   4
#define OFF_REGS   8
#define OFF_MASKS  (8 + NUM_INS * HW_M)
#define OFF_FEAT   (OFF_MASKS + NUM_INS * HW_M)

// ---------------- device scratch ----------------
__device__ float g_hm[HW_H];
__device__ float g_scores[NUM_INS];
__device__ int   g_inds[NUM_INS];
__device__ float g_gp[NUM_INS * NGP];
__device__ float g_pv[128 * 4];
__device__ int   g_pi[128 * 4];
// split conv weights (fp16 hi/lo), layout [tap][oc][c], 16B-aligned for cp.async
__device__ __align__(16) __half g_twh16[9 * MB_CH * C_IN];
__device__ __align__(16) __half g_twl16[9 * MB_CH * C_IN];

// ---------------- helpers ----------------
__device__ __forceinline__ uint32_t smem_u32(const void* p) {
    uint32_t a;
    asm("{ .reg .u64 t; cvta.to.shared.u64 t, %1; cvt.u32.u64 %0, t; }"
        : "=r"(a) : "l"(p));
    return a;
}

__device__ __forceinline__ void mma_fp16(float* c, const uint32_t* a, const uint32_t* b) {
    asm volatile(
        "mma.sync.aligned.m16n8k16.row.col.f32.f16.f16.f32 "
        "{%0,%1,%2,%3}, {%4,%5,%6,%7}, {%8,%9}, {%0,%1,%2,%3};"
        : "+f"(c[0]), "+f"(c[1]), "+f"(c[2]), "+f"(c[3])
        : "r"(a[0]), "r"(a[1]), "r"(a[2]), "r"(a[3]), "r"(b[0]), "r"(b[1]));
}

__device__ __forceinline__ void ldsm4(uint32_t* r, uint32_t addr) {
    asm volatile("ldmatrix.sync.aligned.m8n8.x4.shared.b16 {%0,%1,%2,%3}, [%4];"
        : "=r"(r[0]), "=r"(r[1]), "=r"(r[2]), "=r"(r[3]) : "r"(addr));
}

#define CP_ASYNC16(dst, src) \
    asm volatile("cp.async.ca.shared.global [%0], [%1], 16;" \
                 :: "r"(dst), "l"(src))
#define CP_COMMIT() asm volatile("cp.async.commit_group;" ::: "memory")
#define CP_WAIT0()  asm volatile("cp.async.wait_group 0;" ::: "memory")

// ---------------- kernel 0: split conv weights to fp16 hi/lo, [tap][oc][c] ----------------
__global__ void k_prepw(const float* __restrict__ mb_w) {
    int idx = blockIdx.x * 256 + threadIdx.x;
    if (idx >= 9 * MB_CH * C_IN) return;
    int t = idx / (MB_CH * C_IN);
    int rem = idx % (MB_CH * C_IN);
    int oc = rem >> 8;
    int c = rem & 255;
    float w = mb_w[oc * (C_IN * 9) + c * 9 + t];
    __half hi = __float2half_rn(w);
    __half lo = __float2half_rn(w - __half2float(hi));
    g_twh16[idx] = hi;
    g_twl16[idx] = lo;
}

// ---------------- kernel 1: heatmap head ----------------
__global__ void k_hm(const float* __restrict__ out1,
                     const float* __restrict__ hm_w,
                     const float* __restrict__ hm_b) {
    int p = blockIdx.x * 256 + threadIdx.x;
    if (p >= HW_H) return;
    float s0 = 0.f, s1 = 0.f, s2 = 0.f, s3 = 0.f;
    #pragma unroll 4
    for (int c = 0; c < C_IN; c += 4) {
        s0 += hm_w[c + 0] * out1[(c + 0) * HW_H + p];
        s1 += hm_w[c + 1] * out1[(c + 1) * HW_H + p];
        s2 += hm_w[c + 2] * out1[(c + 2) * HW_H + p];
        s3 += hm_w[c + 3] * out1[(c + 3) * HW_H + p];
    }
    float s = hm_b[0] + ((s0 + s1) + (s2 + s3));
    float sg = 1.0f / (1.0f + expf(-s));
    sg = fminf(fmaxf(sg, 1e-4f), 1.0f - 1e-4f);
    g_hm[p] = sg;
}

// ---------------- top-k ----------------
__device__ __forceinline__ bool tk_better(float v1, int i1, float v2, int i2) {
    return (v1 > v2) || (v1 == v2 && i1 < i2);
}

template <int NT>
__device__ __forceinline__ void tk_tree_merge(float* sv, int* si, int tid) {
    for (int stride = NT / 2; stride >= 1; stride >>= 1) {
        __syncthreads();
        if (tid < stride) {
            float av[4], cv[4], mv[4];
            int ai[4], ci[4], mi[4];
            #pragma unroll
            for (int j = 0; j < 4; j++) {
                av[j] = sv[tid * 4 + j];            ai[j] = si[tid * 4 + j];
                cv[j] = sv[(tid + stride) * 4 + j]; ci[j] = si[(tid + stride) * 4 + j];
            }
            int pa = 0, pb = 0;
            #pragma unroll
            for (int j = 0; j < 4; j++) {
                if (tk_better(av[pa], ai[pa], cv[pb], ci[pb])) { mv[j] = av[pa]; mi[j] = ai[pa]; pa++; }
                else                                          { mv[j] = cv[pb]; mi[j] = ci[pb]; pb++; }
            }
            #pragma unroll
            for (int j = 0; j < 4; j++) { sv[tid * 4 + j] = mv[j]; si[tid * 4 + j] = mi[j]; }
        }
    }
    __syncthreads();
}

__global__ void k_topk_part() {
    __shared__ float sv[256 * 4];
    __shared__ int   si[256 * 4];
    int tid = threadIdx.x;
    int p = blockIdx.x * 256 + tid;

    float heat = -1.0f;
    int   idx  = 0x7fffffff;
    if (p < HW_H) {
        int y = p / W_H, x = p % W_H;
        float v = g_hm[p];
        float mx = v;
        #pragma unroll
        for (int dy = -1; dy <= 1; dy++) {
            int yy = y + dy;
            if (yy < 0 || yy >= H_H) continue;
            #pragma unroll
            for (int dx = -1; dx <= 1; dx++) {
                int xx = x + dx;
                if (xx < 0 || xx >= W_H) continue;
                mx = fmaxf(mx, g_hm[yy * W_H + xx]);
            }
        }
        heat = (mx == v) ? v : 0.0f;
        idx = p;
    }
    sv[tid * 4 + 0] = heat; si[tid * 4 + 0] = idx;
    #pragma unroll
    for (int j = 1; j < 4; j++) { sv[tid * 4 + j] = -1.0f; si[tid * 4 + j] = 0x7fffffff; }

    tk_tree_merge<256>(sv, si, tid);

    if (tid < 4) {
        g_pv[blockIdx.x * 4 + tid] = sv[tid];
        g_pi[blockIdx.x * 4 + tid] = si[tid];
    }
}

__global__ void k_topk_merge(float* __restrict__ dout) {
    __shared__ float sv[128 * 4];
    __shared__ int   si[128 * 4];
    int tid = threadIdx.x;
    #pragma unroll
    for (int j = 0; j < 4; j++) {
        sv[tid * 4 + j] = g_pv[tid * 4 + j];
        si[tid * 4 + j] = g_pi[tid * 4 + j];
    }
    tk_tree_merge<128>(sv, si, tid);
    if (tid < 4) {
        g_scores[tid] = sv[tid];
        g_inds[tid]   = si[tid];
        dout[OFF_SCORES + tid] = sv[tid];
        dout[OFF_INDS + tid]   = (float)si[tid];
    }
}

// ---------------- kernel 3: gen params at the 4 pixels ----------------
__global__ void k_genparams(const float* __restrict__ out1,
                            const float* __restrict__ params_w,
                            const float* __restrict__ params_b) {
    int w = blockIdx.x * 8 + (threadIdx.x >> 5);
    int lane = threadIdx.x & 31;
    if (w >= NUM_INS * NGP) return;
    int ins = w / NGP;
    int k = w % NGP;
    int p = g_inds[ins];
    const float4* pw = (const float4*)(params_w + k * C_IN);
    float s = 0.0f;
    #pragma unroll
    for (int j = 0; j < 2; j++) {
        float4 wv = pw[lane * 2 + j];
        int c0 = lane * 8 + j * 4;
        s += wv.x * out1[(c0 + 0) * HW_H + p];
        s += wv.y * out1[(c0 + 1) * HW_H + p];
        s += wv.z * out1[(c0 + 2) * HW_H + p];
        s += wv.w * out1[(c0 + 3) * HW_H + p];
    }
    #pragma unroll
    for (int o = 16; o >= 1; o >>= 1)
        s += __shfl_xor_sync(0xffffffffu, s, o);
    if (lane == 0) g_gp[w] = s + params_b[k];
}

// ---------------- kernel 4: mma.sync 2-pass fp16 conv + relu + dynamic heads ----------------
// Per CTA: M=128 pixels (4 rows x 32 cols), N=64 oc, K=2304 (9 taps x 256 c).
// Warp grid 4(M) x 2(N); warp tile 32x32; m16n8k16 fp16, fp32 acc.
// A: single fp16 (activations); B: fp16 hi/lo split (weights). acc += A*Bh + A*Bl.
// smem layout (bytes):
//   [0:2144)       s_gp (536 f)
//   [2144:2400)    s_mb (64 f)
//   [2432:31808)   halo: 204 pixels x 36 u32 (144B rows: 32 fp16-pair words + pad)
//                  (aliased after mainloop as s_f: 128 x 65 floats, spills into B buf)
//   [31872:68736)  B double buffer: 2 x (hi 64x72 fp16 + lo 64x72 fp16) = 2 x 18432
#define CONV_SMEM_BYTES 68864
#define B_BUF_OFF 31872
#define B_BUF_SZ  18432

__global__ __launch_bounds__(256, 2)
void k_conv_heads(const float* __restrict__ out0,
                  const float* __restrict__ mb_b,
                  float* __restrict__ dout) {
    extern __shared__ char smem[];
    uint32_t sb = smem_u32(smem);
    float* s_gp = (float*)smem;
    float* s_mb = (float*)(smem + 2144);
    uint32_t* s_halo = (uint32_t*)(smem + 2432);
    float* s_f = (float*)(smem + 2432);
    uint32_t halo_base = sb + 2432;
    uint32_t b_base = sb + B_BUF_OFF;

    int tid = threadIdx.x;
    int lane = tid & 31;
    int wid = tid >> 5;
    int wm = wid & 3, wn = wid >> 2;
    int x0 = blockIdx.x * 32, y0 = blockIdx.y * 4;

    for (int i = tid; i < NUM_INS * NGP; i += 256) s_gp[i] = g_gp[i];
    if (tid < MB_CH) s_mb[tid] = mb_b[tid];

    // halo staging coords
    int hp_py = y0 - 1 + tid / 34;
    int hp_px = x0 - 1 + tid % 34;
    bool hp_in = (tid < 204) && (hp_py >= 0) && (hp_py < H_M) &&
                 (hp_px >= 0) && (hp_px < W_M);
    const float* hp_base = out0 + hp_py * W_M + hp_px;

    // per-thread cp.async B-staging indices (4 x 16B per thread)
    int bq_tile[4], bq_oc[4], bq_cg[4];
    #pragma unroll
    for (int q = 0; q < 4; q++) {
        int v = tid + q * 256;
        bq_tile[q] = v >> 9;
        bq_oc[q] = (v & 511) >> 3;
        bq_cg[q] = v & 7;
    }

    // per-lane ldmatrix offsets (halo rows 144B, B rows 144B — both 16B-aligned)
    uint32_t a_lane = (uint32_t)((lane & 15) * 144 + (lane >> 4) * 16);
    uint32_t b_lane = (uint32_t)((((lane & 7) + ((lane >> 4) & 1) * 8) * 144) +
                                 ((lane >> 3) & 1) * 16);

    // stage B tiles for iteration it into buffer bu (cp.async, no wait)
    auto stage_B = [&](int bu, int it) {
        int t = it % 9;
        int c0 = (it / 9) * 64;
        const __half* srch = g_twh16 + t * (MB_CH * C_IN) + c0;
        const __half* srcl = g_twl16 + t * (MB_CH * C_IN) + c0;
        uint32_t dst0 = b_base + bu * B_BUF_SZ;
        #pragma unroll
        for (int q = 0; q < 4; q++) {
            const __half* src = (bq_tile[q] ? srcl : srch) + bq_oc[q] * C_IN + bq_cg[q] * 8;
            uint32_t dst = dst0 + (uint32_t)(bq_tile[q] * 9216 + bq_oc[q] * 144 + bq_cg[q] * 16);
            CP_ASYNC16(dst, src);
        }
    };

    auto stage_halo = [&](int chunk) {
        if (tid < 204) {
            int c0 = chunk * 64;
            uint32_t* hrow = s_halo + tid * 36;
            #pragma unroll 4
            for (int j = 0; j < 32; j++) {
                int c = c0 + 2 * j;
                float v0 = hp_in ? hp_base[(size_t)c * HW_M] : 0.0f;
                float v1 = hp_in ? hp_base[(size_t)(c + 1) * HW_M] : 0.0f;
                __half h0 = __float2half_rn(v0);
                __half h1 = __float2half_rn(v1);
                hrow[j] = (uint32_t)__half_as_ushort(h0) |
                          ((uint32_t)__half_as_ushort(h1) << 16);
            }
        }
    };

    float acc[2][4][4];
    #pragma unroll
    for (int i = 0; i < 2; i++)
        #pragma unroll
        for (int j = 0; j < 4; j++)
            #pragma unroll
            for (int q = 0; q < 4; q++) acc[i][j][q] = 0.0f;

    // prologue: B for iter 0 + halo chunk 0
    stage_B(0, 0);
    CP_COMMIT();
    stage_halo(0);
    CP_WAIT0();
    __syncthreads();

    for (int it = 0; it < 36; it++) {
        int bu = it & 1;
        if (it + 1 < 36) { stage_B(bu ^ 1, it + 1); CP_COMMIT(); }

        int t = it % 9;
        int dy = t / 3, dx = t % 3;
        uint32_t a_row = halo_base + (uint32_t)(((wm + dy) * 34 + dx) * 144) + a_lane;
        uint32_t b_row = b_base + bu * B_BUF_SZ + (uint32_t)(wn * 32 * 144) + b_lane;

        #pragma unroll
        for (int kb = 0; kb < 4; kb++) {
            uint32_t bh[4][2], bl[4][2];
            #pragma unroll
            for (int jj = 0; jj < 2; jj++) {
                uint32_t ba = b_row + jj * (16 * 144) + kb * 32;
                uint32_t r[4];
                ldsm4(r, ba);
                bh[jj * 2][0] = r[0]; bh[jj * 2][1] = r[1];
                bh[jj * 2 + 1][0] = r[2]; bh[jj * 2 + 1][1] = r[3];
                ldsm4(r, ba + 9216);
                bl[jj * 2][0] = r[0]; bl[jj * 2][1] = r[1];
                bl[jj * 2 + 1][0] = r[2]; bl[jj * 2 + 1][1] = r[3];
            }
            #pragma unroll
            for (int i = 0; i < 2; i++) {
                uint32_t ah[4];
                ldsm4(ah, a_row + i * (16 * 144) + kb * 32);
                #pragma unroll
                for (int j = 0; j < 4; j++) {
                    mma_fp16(acc[i][j], ah, bh[j]);
                    mma_fp16(acc[i][j], ah, bl[j]);
                }
            }
        }

        if (t == 8 && it + 1 < 36) {
            __syncthreads();          // all warps done reading this chunk's halo
            stage_halo((it + 1) / 9);
        }
        CP_WAIT0();
        __syncthreads();
    }

    // ---- epilogue: bias + relu into s_f (aliases halo+B), then dynamic heads ----
    {
        int mrow = wm * 32 + (lane >> 2);
        int ocb = wn * 32 + (lane & 3) * 2;
        #pragma unroll
        for (int i = 0; i < 2; i++)
            #pragma unroll
            for (int j = 0; j < 4; j++) {
                int m = mrow + i * 16;
                int oc = ocb + j * 8;
                s_f[m * 65 + oc]           = fmaxf(acc[i][j][0] + s_mb[oc], 0.0f);
                s_f[m * 65 + oc + 1]       = fmaxf(acc[i][j][1] + s_mb[oc + 1], 0.0f);
                s_f[(m + 8) * 65 + oc]     = fmaxf(acc[i][j][2] + s_mb[oc], 0.0f);
                s_f[(m + 8) * 65 + oc + 1] = fmaxf(acc[i][j][3] + s_mb[oc + 1], 0.0f);
            }
    }
    __syncthreads();

    if (tid < 128) {
        float f[64];
        #pragma unroll
        for (int k = 0; k < 64; k++) f[k] = s_f[tid * 65 + k];

        int ar = tid >> 5, ax = tid & 31;
        int gx = x0 + ax, gy = y0 + ar;
        float xx = -1.0f + 2.0f * (float)gx / (float)(W_M - 1);
        float yy = -1.0f + 2.0f * (float)gy / (float)(H_M - 1);
        int pix = gy * W_M + gx;

        #pragma unroll
        for (int ins = 0; ins < NUM_INS; ins++) {
            const float* gp = s_gp + ins * NGP;
            float m  = gp[66]  + gp[64] * xx + gp[65] * yy;
            float rr = gp[133] + gp[NMP + 64] * xx + gp[NMP + 65] * yy;
            #pragma unroll
            for (int k = 0; k < 64; k++) {
                m  += gp[k] * f[k];
                rr += gp[NMP + k] * f[k];
            }
            dout[OFF_MASKS + ins * HW_M + pix] = m;
            dout[OFF_REGS  + ins * HW_M + pix] = rr;
        }
    }
}

// ---------------- kernel 5: per-column MLP over masks0 ----------------
__global__ void k_mlp(const float* __restrict__ w1, const float* __restrict__ b1,
                      const float* __restrict__ w2, const float* __restrict__ b2,
                      float* __restrict__ dout) {
    __shared__ float sh[4][HID];
    int tid = threadIdx.x;
    int lcol = tid / HID;
    int j = tid % HID;
    int g = blockIdx.x * 4 + lcol;
    int ins = g / W_M;
    int x = g % W_M;
    const float* mbase = dout + OFF_MASKS + ins * HW_M + x;
    float s0 = 0.f, s1 = 0.f, s2 = 0.f, s3 = 0.f;
    #pragma unroll 2
    for (int y = 0; y < H_M; y += 4) {
        s0 += mbase[(y + 0) * W_M] * w1[(y + 0) * HID + j];
        s1 += mbase[(y + 1) * W_M] * w1[(y + 1) * HID + j];
        s2 += mbase[(y + 2) * W_M] * w1[(y + 2) * HID + j];
        s3 += mbase[(y + 3) * W_M] * w1[(y + 3) * HID + j];
    }
    float s = b1[j] + ((s0 + s1) + (s2 + s3));
    sh[lcol][j] = fmaxf(s, 0.0f);
    __syncthreads();
    if (tid < 8) {
        int lc = tid >> 1, j2 = tid & 1;
        int gg = blockIdx.x * 4 + lc;
        float s2f = b2[j2];
        #pragma unroll
        for (int jj = 0; jj < HID; jj++)
            s2f += sh[lc][jj] * w2[jj * 2 + j2];
        dout[OFF_FEAT + gg * 2 + j2] = s2f;
    }
}

// ---------------- launcher ----------------
extern "C" void kernel_launch(void* const* d_in, const int* in_sizes, int n_in,
                              void* d_out, int out_size) {
    const float* out0     = (const float*)d_in[0];
    const float* out1     = (const float*)d_in[1];
    const float* hm_w     = (const float*)d_in[2];
    const float* hm_b     = (const float*)d_in[3];
    const float* params_w = (const float*)d_in[4];
    const float* params_b = (const float*)d_in[5];
    const float* mb_w     = (const float*)d_in[6];
    const float* mb_b     = (const float*)d_in[7];
    const float* mlp_w1   = (const float*)d_in[8];
    const float* mlp_b1   = (const float*)d_in[9];
    const float* mlp_w2   = (const float*)d_in[10];
    const float* mlp_b2   = (const float*)d_in[11];
    float* dout = (float*)d_out;

    cudaFuncSetAttribute(k_conv_heads,
                         cudaFuncAttributeMaxDynamicSharedMemorySize,
                         CONV_SMEM_BYTES);

    k_prepw<<<(9 * MB_CH * C_IN + 255) / 256, 256>>>(mb_w);
    k_hm<<<(HW_H + 255) / 256, 256>>>(out1, hm_w, hm_b);
    k_topk_part<<<128, 256>>>();
    k_topk_merge<<<1, 128>>>(dout);
    k_genparams<<<67, 256>>>(out1, params_w, params_b);
    dim3 cgrid(W_M / 32, H_M / 4);
    k_conv_heads<<<cgrid, 256, CONV_SMEM_BYTES>>>(out0, mb_b, dout);
    k_mlp<<<(NUM_INS * W_M) / 4, 256>>>(mlp_w1, mlp_b1, mlp_w2, mlp_b2, dout);
}

// round 8
// speedup vs baseline: 7.5938x; 1.2726x over previous
#include <cuda_runtime.h>
#include <cuda_bf16.h>
#include <cuda_fp16.h>
#include <math.h>
#include <stdint.h>

// ---------------- problem constants ----------------
#define C_IN     256
#define H_M      272
#define W_M      480
#define HW_M     (H_M * W_M)          // 130560
#define H_H      136
#define W_H      240
#define HW_H     (H_H * W_H)          // 32640
#define MB_CH    64
#define NUM_INS  4
#define NGP      134
#define NMP      67
#define HID      64

#define OFF_SCORES 0
#define OFF_INDS   4
#define OFF_REGS   8
#define OFF_MASKS  (8 + NUM_INS * HW_M)
#define OFF_FEAT   (OFF_MASKS + NUM_INS * HW_M)

// ---------------- device scratch ----------------
__device__ float g_hm[HW_H];
__device__ float g_scores[NUM_INS];
__device__ int   g_inds[NUM_INS];
__device__ float g_gp[NUM_INS * NGP];
__device__ float g_pv[128 * 4];
__device__ int   g_pi[128 * 4];
// conv weights fp16, layout [tap][oc][c], 16B-aligned for cp.async
__device__ __align__(16) __half g_tw16[9 * MB_CH * C_IN];

// ---------------- helpers ----------------
__device__ __forceinline__ uint32_t smem_u32(const void* p) {
    uint32_t a;
    asm("{ .reg .u64 t; cvta.to.shared.u64 t, %1; cvt.u32.u64 %0, t; }"
        : "=r"(a) : "l"(p));
    return a;
}

__device__ __forceinline__ void mma_fp16(float* c, const uint32_t* a, const uint32_t* b) {
    asm volatile(
        "mma.sync.aligned.m16n8k16.row.col.f32.f16.f16.f32 "
        "{%0,%1,%2,%3}, {%4,%5,%6,%7}, {%8,%9}, {%0,%1,%2,%3};"
        : "+f"(c[0]), "+f"(c[1]), "+f"(c[2]), "+f"(c[3])
        : "r"(a[0]), "r"(a[1]), "r"(a[2]), "r"(a[3]), "r"(b[0]), "r"(b[1]));
}

__device__ __forceinline__ void ldsm4(uint32_t* r, uint32_t addr) {
    asm volatile("ldmatrix.sync.aligned.m8n8.x4.shared.b16 {%0,%1,%2,%3}, [%4];"
        : "=r"(r[0]), "=r"(r[1]), "=r"(r[2]), "=r"(r[3]) : "r"(addr));
}

#define CP_ASYNC16(dst, src) \
    asm volatile("cp.async.ca.shared.global [%0], [%1], 16;" \
                 :: "r"(dst), "l"(src))
#define CP_COMMIT() asm volatile("cp.async.commit_group;" ::: "memory")
#define CP_WAIT0()  asm volatile("cp.async.wait_group 0;" ::: "memory")

// ---------------- kernel 0: conv weights -> fp16, [tap][oc][c] ----------------
__global__ void k_prepw(const float* __restrict__ mb_w) {
    int idx = blockIdx.x * 256 + threadIdx.x;
    if (idx >= 9 * MB_CH * C_IN) return;
    int t = idx / (MB_CH * C_IN);
    int rem = idx % (MB_CH * C_IN);
    int oc = rem >> 8;
    int c = rem & 255;
    float w = mb_w[oc * (C_IN * 9) + c * 9 + t];
    g_tw16[idx] = __float2half_rn(w);
}

// ---------------- kernel 1: heatmap head ----------------
__global__ void k_hm(const float* __restrict__ out1,
                     const float* __restrict__ hm_w,
                     const float* __restrict__ hm_b) {
    int p = blockIdx.x * 256 + threadIdx.x;
    if (p >= HW_H) return;
    float s0 = 0.f, s1 = 0.f, s2 = 0.f, s3 = 0.f;
    #pragma unroll 4
    for (int c = 0; c < C_IN; c += 4) {
        s0 += hm_w[c + 0] * out1[(c + 0) * HW_H + p];
        s1 += hm_w[c + 1] * out1[(c + 1) * HW_H + p];
        s2 += hm_w[c + 2] * out1[(c + 2) * HW_H + p];
        s3 += hm_w[c + 3] * out1[(c + 3) * HW_H + p];
    }
    float s = hm_b[0] + ((s0 + s1) + (s2 + s3));
    float sg = 1.0f / (1.0f + expf(-s));
    sg = fminf(fmaxf(sg, 1e-4f), 1.0f - 1e-4f);
    g_hm[p] = sg;
}

// ---------------- top-k ----------------
__device__ __forceinline__ bool tk_better(float v1, int i1, float v2, int i2) {
    return (v1 > v2) || (v1 == v2 && i1 < i2);
}

template <int NT>
__device__ __forceinline__ void tk_tree_merge(float* sv, int* si, int tid) {
    for (int stride = NT / 2; stride >= 1; stride >>= 1) {
        __syncthreads();
        if (tid < stride) {
            float av[4], cv[4], mv[4];
            int ai[4], ci[4], mi[4];
            #pragma unroll
            for (int j = 0; j < 4; j++) {
                av[j] = sv[tid * 4 + j];            ai[j] = si[tid * 4 + j];
                cv[j] = sv[(tid + stride) * 4 + j]; ci[j] = si[(tid + stride) * 4 + j];
            }
            int pa = 0, pb = 0;
            #pragma unroll
            for (int j = 0; j < 4; j++) {
                if (tk_better(av[pa], ai[pa], cv[pb], ci[pb])) { mv[j] = av[pa]; mi[j] = ai[pa]; pa++; }
                else                                          { mv[j] = cv[pb]; mi[j] = ci[pb]; pb++; }
            }
            #pragma unroll
            for (int j = 0; j < 4; j++) { sv[tid * 4 + j] = mv[j]; si[tid * 4 + j] = mi[j]; }
        }
    }
    __syncthreads();
}

__global__ void k_topk_part() {
    __shared__ float sv[256 * 4];
    __shared__ int   si[256 * 4];
    int tid = threadIdx.x;
    int p = blockIdx.x * 256 + tid;

    float heat = -1.0f;
    int   idx  = 0x7fffffff;
    if (p < HW_H) {
        int y = p / W_H, x = p % W_H;
        float v = g_hm[p];
        float mx = v;
        #pragma unroll
        for (int dy = -1; dy <= 1; dy++) {
            int yy = y + dy;
            if (yy < 0 || yy >= H_H) continue;
            #pragma unroll
            for (int dx = -1; dx <= 1; dx++) {
                int xx = x + dx;
                if (xx < 0 || xx >= W_H) continue;
                mx = fmaxf(mx, g_hm[yy * W_H + xx]);
            }
        }
        heat = (mx == v) ? v : 0.0f;
        idx = p;
    }
    sv[tid * 4 + 0] = heat; si[tid * 4 + 0] = idx;
    #pragma unroll
    for (int j = 1; j < 4; j++) { sv[tid * 4 + j] = -1.0f; si[tid * 4 + j] = 0x7fffffff; }

    tk_tree_merge<256>(sv, si, tid);

    if (tid < 4) {
        g_pv[blockIdx.x * 4 + tid] = sv[tid];
        g_pi[blockIdx.x * 4 + tid] = si[tid];
    }
}

__global__ void k_topk_merge(float* __restrict__ dout) {
    __shared__ float sv[128 * 4];
    __shared__ int   si[128 * 4];
    int tid = threadIdx.x;
    #pragma unroll
    for (int j = 0; j < 4; j++) {
        sv[tid * 4 + j] = g_pv[tid * 4 + j];
        si[tid * 4 + j] = g_pi[tid * 4 + j];
    }
    tk_tree_merge<128>(sv, si, tid);
    if (tid < 4) {
        g_scores[tid] = sv[tid];
        g_inds[tid]   = si[tid];
        dout[OFF_SCORES + tid] = sv[tid];
        dout[OFF_INDS + tid]   = (float)si[tid];
    }
}

// ---------------- kernel 3: gen params at the 4 pixels ----------------
__global__ void k_genparams(const float* __restrict__ out1,
                            const float* __restrict__ params_w,
                            const float* __restrict__ params_b) {
    int w = blockIdx.x * 8 + (threadIdx.x >> 5);
    int lane = threadIdx.x & 31;
    if (w >= NUM_INS * NGP) return;
    int ins = w / NGP;
    int k = w % NGP;
    int p = g_inds[ins];
    const float4* pw = (const float4*)(params_w + k * C_IN);
    float s = 0.0f;
    #pragma unroll
    for (int j = 0; j < 2; j++) {
        float4 wv = pw[lane * 2 + j];
        int c0 = lane * 8 + j * 4;
        s += wv.x * out1[(c0 + 0) * HW_H + p];
        s += wv.y * out1[(c0 + 1) * HW_H + p];
        s += wv.z * out1[(c0 + 2) * HW_H + p];
        s += wv.w * out1[(c0 + 3) * HW_H + p];
    }
    #pragma unroll
    for (int o = 16; o >= 1; o >>= 1)
        s += __shfl_xor_sync(0xffffffffu, s, o);
    if (lane == 0) g_gp[w] = s + params_b[k];
}

// ---------------- kernel 4: mma.sync single-pass fp16 conv + relu + dynamic heads ----------------
// Per CTA: M=128 pixels (4 rows x 32 cols), N=64 oc, K=2304 (9 taps x 256 c).
// Warp grid 4(M) x 2(N); warp tile 32x32; m16n8k16 fp16, fp32 acc.
// A: fp16 activations; B: fp16 weights. acc += A*B.
// smem layout (bytes):
//   [0:2144)       s_gp (536 f)
//   [2144:2400)    s_mb (64 f)
//   [2432:31808)   halo: 204 pixels x 36 u32 (144B rows: 32 fp16-pair words + pad)
//                  (aliased after mainloop as s_f: 128 x 65 floats, spills into B buf)
//   [31872:50304)  B double buffer: 2 x (64x72 fp16) = 2 x 9216
#define CONV_SMEM_BYTES 50432
#define B_BUF_OFF 31872
#define B_BUF_SZ  9216

__global__ __launch_bounds__(256, 2)
void k_conv_heads(const float* __restrict__ out0,
                  const float* __restrict__ mb_b,
                  float* __restrict__ dout) {
    extern __shared__ char smem[];
    uint32_t sb = smem_u32(smem);
    float* s_gp = (float*)smem;
    float* s_mb = (float*)(smem + 2144);
    uint32_t* s_halo = (uint32_t*)(smem + 2432);
    float* s_f = (float*)(smem + 2432);
    uint32_t halo_base = sb + 2432;
    uint32_t b_base = sb + B_BUF_OFF;

    int tid = threadIdx.x;
    int lane = tid & 31;
    int wid = tid >> 5;
    int wm = wid & 3, wn = wid >> 2;
    int x0 = blockIdx.x * 32, y0 = blockIdx.y * 4;

    for (int i = tid; i < NUM_INS * NGP; i += 256) s_gp[i] = g_gp[i];
    if (tid < MB_CH) s_mb[tid] = mb_b[tid];

    // halo staging coords
    int hp_py = y0 - 1 + tid / 34;
    int hp_px = x0 - 1 + tid % 34;
    bool hp_in = (tid < 204) && (hp_py >= 0) && (hp_py < H_M) &&
                 (hp_px >= 0) && (hp_px < W_M);
    const float* hp_base = out0 + hp_py * W_M + hp_px;

    // per-thread cp.async B-staging indices (2 x 16B per thread)
    int bq_oc[2], bq_cg[2];
    #pragma unroll
    for (int q = 0; q < 2; q++) {
        int v = tid + q * 256;
        bq_oc[q] = v >> 3;
        bq_cg[q] = v & 7;
    }

    // per-lane ldmatrix offsets (144B rows, 16B-aligned)
    uint32_t a_lane = (uint32_t)((lane & 15) * 144 + (lane >> 4) * 16);
    uint32_t b_lane = (uint32_t)((((lane & 7) + ((lane >> 4) & 1) * 8) * 144) +
                                 ((lane >> 3) & 1) * 16);

    // stage B tile for iteration it into buffer bu (cp.async, no wait)
    auto stage_B = [&](int bu, int it) {
        int t = it % 9;
        int c0 = (it / 9) * 64;
        const __half* src0 = g_tw16 + t * (MB_CH * C_IN) + c0;
        uint32_t dst0 = b_base + bu * B_BUF_SZ;
        #pragma unroll
        for (int q = 0; q < 2; q++) {
            const __half* src = src0 + bq_oc[q] * C_IN + bq_cg[q] * 8;
            uint32_t dst = dst0 + (uint32_t)(bq_oc[q] * 144 + bq_cg[q] * 16);
            CP_ASYNC16(dst, src);
        }
    };

    auto stage_halo = [&](int chunk) {
        if (tid < 204) {
            int c0 = chunk * 64;
            uint32_t* hrow = s_halo + tid * 36;
            #pragma unroll 4
            for (int j = 0; j < 32; j++) {
                int c = c0 + 2 * j;
                float v0 = hp_in ? hp_base[(size_t)c * HW_M] : 0.0f;
                float v1 = hp_in ? hp_base[(size_t)(c + 1) * HW_M] : 0.0f;
                __half h0 = __float2half_rn(v0);
                __half h1 = __float2half_rn(v1);
                hrow[j] = (uint32_t)__half_as_ushort(h0) |
                          ((uint32_t)__half_as_ushort(h1) << 16);
            }
        }
    };

    float acc[2][4][4];
    #pragma unroll
    for (int i = 0; i < 2; i++)
        #pragma unroll
        for (int j = 0; j < 4; j++)
            #pragma unroll
            for (int q = 0; q < 4; q++) acc[i][j][q] = 0.0f;

    // prologue: B for iter 0 + halo chunk 0
    stage_B(0, 0);
    CP_COMMIT();
    stage_halo(0);
    CP_WAIT0();
    __syncthreads();

    for (int it = 0; it < 36; it++) {
        int bu = it & 1;
        if (it + 1 < 36) { stage_B(bu ^ 1, it + 1); CP_COMMIT(); }

        int t = it % 9;
        int dy = t / 3, dx = t % 3;
        uint32_t a_row = halo_base + (uint32_t)(((wm + dy) * 34 + dx) * 144) + a_lane;
        uint32_t b_row = b_base + bu * B_BUF_SZ + (uint32_t)(wn * 32 * 144) + b_lane;

        #pragma unroll
        for (int kb = 0; kb < 4; kb++) {
            uint32_t bh[4][2];
            #pragma unroll
            for (int jj = 0; jj < 2; jj++) {
                uint32_t ba = b_row + jj * (16 * 144) + kb * 32;
                uint32_t r[4];
                ldsm4(r, ba);
                bh[jj * 2][0] = r[0]; bh[jj * 2][1] = r[1];
                bh[jj * 2 + 1][0] = r[2]; bh[jj * 2 + 1][1] = r[3];
            }
            #pragma unroll
            for (int i = 0; i < 2; i++) {
                uint32_t ah[4];
                ldsm4(ah, a_row + i * (16 * 144) + kb * 32);
                #pragma unroll
                for (int j = 0; j < 4; j++)
                    mma_fp16(acc[i][j], ah, bh[j]);
            }
        }

        if (t == 8 && it + 1 < 36) {
            __syncthreads();          // all warps done reading this chunk's halo
            stage_halo((it + 1) / 9);
        }
        CP_WAIT0();
        __syncthreads();
    }

    // ---- epilogue: bias + relu into s_f (aliases halo+B), then dynamic heads ----
    {
        int mrow = wm * 32 + (lane >> 2);
        int ocb = wn * 32 + (lane & 3) * 2;
        #pragma unroll
        for (int i = 0; i < 2; i++)
            #pragma unroll
            for (int j = 0; j < 4; j++) {
                int m = mrow + i * 16;
                int oc = ocb + j * 8;
                s_f[m * 65 + oc]           = fmaxf(acc[i][j][0] + s_mb[oc], 0.0f);
                s_f[m * 65 + oc + 1]       = fmaxf(acc[i][j][1] + s_mb[oc + 1], 0.0f);
                s_f[(m + 8) * 65 + oc]     = fmaxf(acc[i][j][2] + s_mb[oc], 0.0f);
                s_f[(m + 8) * 65 + oc + 1] = fmaxf(acc[i][j][3] + s_mb[oc + 1], 0.0f);
            }
    }
    __syncthreads();

    if (tid < 128) {
        float f[64];
        #pragma unroll
        for (int k = 0; k < 64; k++) f[k] = s_f[tid * 65 + k];

        int ar = tid >> 5, ax = tid & 31;
        int gx = x0 + ax, gy = y0 + ar;
        float xx = -1.0f + 2.0f * (float)gx / (float)(W_M - 1);
        float yy = -1.0f + 2.0f * (float)gy / (float)(H_M - 1);
        int pix = gy * W_M + gx;

        #pragma unroll
        for (int ins = 0; ins < NUM_INS; ins++) {
            const float* gp = s_gp + ins * NGP;
            float m  = gp[66]  + gp[64] * xx + gp[65] * yy;
            float rr = gp[133] + gp[NMP + 64] * xx + gp[NMP + 65] * yy;
            #pragma unroll
            for (int k = 0; k < 64; k++) {
                m  += gp[k] * f[k];
                rr += gp[NMP + k] * f[k];
            }
            dout[OFF_MASKS + ins * HW_M + pix] = m;
            dout[OFF_REGS  + ins * HW_M + pix] = rr;
        }
    }
}

// ---------------- kernel 5: per-column MLP over masks0 ----------------
__global__ void k_mlp(const float* __restrict__ w1, const float* __restrict__ b1,
                      const float* __restrict__ w2, const float* __restrict__ b2,
                      float* __restrict__ dout) {
    __shared__ float sh[4][HID];
    int tid = threadIdx.x;
    int lcol = tid / HID;
    int j = tid % HID;
    int g = blockIdx.x * 4 + lcol;
    int ins = g / W_M;
    int x = g % W_M;
    const float* mbase = dout + OFF_MASKS + ins * HW_M + x;
    float s0 = 0.f, s1 = 0.f, s2 = 0.f, s3 = 0.f;
    #pragma unroll 2
    for (int y = 0; y < H_M; y += 4) {
        s0 += mbase[(y + 0) * W_M] * w1[(y + 0) * HID + j];
        s1 += mbase[(y + 1) * W_M] * w1[(y + 1) * HID + j];
        s2 += mbase[(y + 2) * W_M] * w1[(y + 2) * HID + j];
        s3 += mbase[(y + 3) * W_M] * w1[(y + 3) * HID + j];
    }
    float s = b1[j] + ((s0 + s1) + (s2 + s3));
    sh[lcol][j] = fmaxf(s, 0.0f);
    __syncthreads();
    if (tid < 8) {
        int lc = tid >> 1, j2 = tid & 1;
        int gg = blockIdx.x * 4 + lc;
        float s2f = b2[j2];
        #pragma unroll
        for (int jj = 0; jj < HID; jj++)
            s2f += sh[lc][jj] * w2[jj * 2 + j2];
        dout[OFF_FEAT + gg * 2 + j2] = s2f;
    }
}

// ---------------- launcher ----------------
extern "C" void kernel_launch(void* const* d_in, const int* in_sizes, int n_in,
                              void* d_out, int out_size) {
    const float* out0     = (const float*)d_in[0];
    const float* out1     = (const float*)d_in[1];
    const float* hm_w     = (const float*)d_in[2];
    const float* hm_b     = (const float*)d_in[3];
    const float* params_w = (const float*)d_in[4];
    const float* params_b = (const float*)d_in[5];
    const float* mb_w     = (const float*)d_in[6];
    const float* mb_b     = (const float*)d_in[7];
    const float* mlp_w1   = (const float*)d_in[8];
    const float* mlp_b1   = (const float*)d_in[9];
    const float* mlp_w2   = (const float*)d_in[10];
    const float* mlp_b2   = (const float*)d_in[11];
    float* dout = (float*)d_out;

    cudaFuncSetAttribute(k_conv_heads,
                         cudaFuncAttributeMaxDynamicSharedMemorySize,
                         CONV_SMEM_BYTES);

    k_prepw<<<(9 * MB_CH * C_IN + 255) / 256, 256>>>(mb_w);
    k_hm<<<(HW_H + 255) / 256, 256>>>(out1, hm_w, hm_b);
    k_topk_part<<<128, 256>>>();
    k_topk_merge<<<1, 128>>>(dout);
    k_genparams<<<67, 256>>>(out1, params_w, params_b);
    dim3 cgrid(W_M / 32, H_M / 4);
    k_conv_heads<<<cgrid, 256, CONV_SMEM_BYTES>>>(out0, mb_b, dout);
    k_mlp<<<(NUM_INS * W_M) / 4, 256>>>(mlp_w1, mlp_b1, mlp_w2, mlp_b2, dout);
}